// round 2
// baseline (speedup 1.0000x reference)
#include <cuda_runtime.h>

#define B 16
#define NN 1024
#define NF 16
#define NHID 32
#define HEADS 4
#define NP 12
#define WT_STRIDE 1028   // 1028 % 32 == 4 -> conflict-free LDS.128 per 8-lane phase

// ---------------- scratch (device globals; no allocation allowed) ----------------
__device__ float    g_Wh[B*HEADS*NN*NHID];     // 8 MB  [b][h][n][k]
__device__ float    g_fsrc[B*HEADS*NN];
__device__ float    g_fdst[B*HEADS*NN];
__device__ unsigned g_mask[NN*NN/32];          // adj>0 packed bits, [i][jword]
__device__ float    g_h[B*NN*HEADS*NHID];      // 8 MB  [b][n][h*32+k]
__device__ float    g_Wh2[B*NN*NP];            // [b][n][p]
__device__ float    g_gsrc[B*NN];
__device__ float    g_gdst[B*NN];

// ---------------- K0: pack adjacency to bitmask ----------------
__global__ void k_mask(const int* __restrict__ adj) {
    int i = blockIdx.x;
    int j = threadIdx.x;
    unsigned bal = __ballot_sync(0xffffffffu, adj[i*NN + j] > 0);
    if ((j & 31) == 0) g_mask[i*32 + (j >> 5)] = bal;
}

// ---------------- K1: Wh = x@W per head, f_src/f_dst dots ----------------
__global__ void k_wh(const float* __restrict__ x, const float* __restrict__ W,
                     const float* __restrict__ a_src, const float* __restrict__ a_dst) {
    __shared__ float Ws[NF*NHID];
    __shared__ float as_s[NHID], ad_s[NHID];
    int bh = blockIdx.x;
    int b = bh >> 2, h = bh & 3;
    int tid = threadIdx.x;
    for (int i = tid; i < NF*NHID; i += 256) Ws[i] = W[h*NF*NHID + i];
    if (tid < NHID) { as_s[tid] = a_src[h*NHID + tid]; ad_s[tid] = a_dst[h*NHID + tid]; }
    __syncthreads();

    int n = blockIdx.y*256 + tid;
    const float4* xp = (const float4*)(x + ((size_t)b*NN + n)*NF);
    float xf[NF];
#pragma unroll
    for (int i = 0; i < NF/4; i++) {
        float4 v = __ldg(xp + i);
        xf[4*i] = v.x; xf[4*i+1] = v.y; xf[4*i+2] = v.z; xf[4*i+3] = v.w;
    }
    float wh[NHID];
#pragma unroll
    for (int k = 0; k < NHID; k++) wh[k] = 0.f;
#pragma unroll
    for (int f = 0; f < NF; f++) {
        float xv = xf[f];
#pragma unroll
        for (int k = 0; k < NHID; k++) wh[k] += xv * Ws[f*NHID + k];
    }
    float fs = 0.f, fd = 0.f;
#pragma unroll
    for (int k = 0; k < NHID; k++) { fs += wh[k]*as_s[k]; fd += wh[k]*ad_s[k]; }

    float* op = g_Wh + ((size_t)bh*NN + n)*NHID;
#pragma unroll
    for (int k = 0; k < NHID; k += 4)
        *(float4*)(op + k) = make_float4(wh[k], wh[k+1], wh[k+2], wh[k+3]);
    g_fsrc[bh*NN + n] = fs;
    g_fdst[bh*NN + n] = fd;
}

// ---------------- K2: fused masked softmax + attn@Wh + ELU (layer 1) ----------------
// CTA = (b,h,half of rows). smem: WhT[32][1028] + f_dst[1024] + per-warp p tile.
// Warp owns 8 rows; lane = output component k. No max-subtraction needed (|e|<~4).
__global__ void __launch_bounds__(512, 1) k_attn1() {
    extern __shared__ float sm[];
    float* WhT  = sm;                        // 32*1028
    float* fd_s = sm + 32*WT_STRIDE;         // 1024
    float* p_s  = fd_s + NN;                 // 16 warps * 256

    int bh   = blockIdx.x >> 1;
    int half = blockIdx.x & 1;
    int b = bh >> 2, h = bh & 3;
    int tid = threadIdx.x;

    const float* Whg = g_Wh + (size_t)bh*NN*NHID;
    for (int idx = tid; idx < NN*NHID; idx += 512) {
        int j = idx >> 5, k = idx & 31;
        WhT[k*WT_STRIDE + j] = Whg[idx];
    }
    for (int idx = tid; idx < NN; idx += 512) fd_s[idx] = g_fdst[bh*NN + idx];
    __syncthreads();

    int warp = tid >> 5, lane = tid & 31;
    int rl = lane & 7;        // row this lane produces p for
    int tq = lane >> 3;       // 0..3
    float* pw = p_s + warp*256;

#pragma unroll 1
    for (int pass = 0; pass < 4; pass++) {
        int row0 = half*512 + pass*128 + warp*8;
        float fs = g_fsrc[bh*NN + row0 + rl];
        const unsigned* mrow = g_mask + (size_t)(row0 + rl)*32;

        float acc[8];
#pragma unroll
        for (int r = 0; r < 8; r++) acc[r] = 0.f;
        float zp = 0.f;

#pragma unroll 1
        for (int jb = 0; jb < NN; jb += 32) {
            unsigned mw = __ldg(mrow + (jb >> 5));
            // produce p[t][r] tile: lane writes words lane+32c -> conflict-free STS
#pragma unroll
            for (int c = 0; c < 8; c++) {
                int t = tq + 4*c;
                float e = fs + fd_s[jb + t];
                e = e > 0.f ? e : 0.2f*e;
                float p = ((mw >> t) & 1u) ? __expf(e) : 0.f;
                zp += p;
                pw[t*8 + rl] = p;
            }
            float wh[32];
#pragma unroll
            for (int u = 0; u < 8; u++) {
                float4 v = *(const float4*)&WhT[lane*WT_STRIDE + jb + 4*u];
                wh[4*u] = v.x; wh[4*u+1] = v.y; wh[4*u+2] = v.z; wh[4*u+3] = v.w;
            }
            __syncwarp();
#pragma unroll
            for (int t = 0; t < 32; t++) {
                float wv = wh[t];
                float4 pA = *(const float4*)&pw[t*8];
                float4 pB = *(const float4*)&pw[t*8 + 4];
                acc[0] += pA.x*wv; acc[1] += pA.y*wv; acc[2] += pA.z*wv; acc[3] += pA.w*wv;
                acc[4] += pB.x*wv; acc[5] += pB.y*wv; acc[6] += pB.z*wv; acc[7] += pB.w*wv;
            }
            __syncwarp();
        }

        // Z per row: lanes {r, r+8, r+16, r+24} hold partials for row r
        zp += __shfl_xor_sync(0xffffffffu, zp, 8);
        zp += __shfl_xor_sync(0xffffffffu, zp, 16);
#pragma unroll
        for (int r = 0; r < 8; r++) {
            float Zr = __shfl_sync(0xffffffffu, zp, r);
            float v = acc[r] / Zr;
            v = v > 0.f ? v : (__expf(v) - 1.f);   // ELU
            g_h[((size_t)b*NN + row0 + r)*(HEADS*NHID) + h*NHID + lane] = v;
        }
    }
}

// ---------------- K3: Wh2 = h@W_out, g_src/g_dst dots ----------------
__global__ void k_wh2(const float* __restrict__ W_out,
                      const float* __restrict__ ao_src, const float* __restrict__ ao_dst) {
    __shared__ float Wo[128*NP];
    __shared__ float aos[NP], aod[NP];
    int tid = threadIdx.x;
    for (int i = tid; i < 128*NP; i += 256) Wo[i] = W_out[i];
    if (tid < NP) { aos[tid] = ao_src[tid]; aod[tid] = ao_dst[tid]; }
    __syncthreads();

    int bn = blockIdx.x*256 + tid;
    const float* hp = g_h + (size_t)bn*128;
    float o[NP];
#pragma unroll
    for (int p = 0; p < NP; p++) o[p] = 0.f;
    for (int d = 0; d < 128; d += 4) {
        float4 hv = *(const float4*)(hp + d);
        float hh[4] = {hv.x, hv.y, hv.z, hv.w};
#pragma unroll
        for (int q = 0; q < 4; q++) {
#pragma unroll
            for (int p = 0; p < NP; p++) o[p] += hh[q]*Wo[(d+q)*NP + p];
        }
    }
    float gs = 0.f, gd = 0.f;
#pragma unroll
    for (int p = 0; p < NP; p++) { gs += o[p]*aos[p]; gd += o[p]*aod[p]; }
    float* op = g_Wh2 + (size_t)bn*NP;
#pragma unroll
    for (int p = 0; p < NP; p++) op[p] = o[p];
    g_gsrc[bn] = gs;
    g_gdst[bn] = gd;
}

// ---------------- K4: fused masked softmax + attn2@Wh2 + ELU (layer 2) ----------------
__global__ void __launch_bounds__(512, 1) k_attn2(float* __restrict__ out) {
    extern __shared__ float sm[];
    float* Vs   = sm;           // 1024*12
    float* gd_s = sm + NN*NP;   // 1024
    int b = blockIdx.x >> 3;
    int chunk = blockIdx.x & 7;
    int tid = threadIdx.x;

    const float* Vg = g_Wh2 + (size_t)b*NN*NP;
    for (int i = tid; i < NN*NP; i += 512) Vs[i] = Vg[i];
    for (int i = tid; i < NN; i += 512) gd_s[i] = g_gdst[b*NN + i];
    __syncthreads();

    int warp = tid >> 5, lane = tid & 31;
#pragma unroll 1
    for (int rr = 0; rr < 8; rr++) {
        int i = chunk*128 + warp*8 + rr;
        float fs = g_gsrc[b*NN + i];
        const unsigned* mrow = g_mask + (size_t)i*32;
        float acc[NP];
#pragma unroll
        for (int p = 0; p < NP; p++) acc[p] = 0.f;
        float z = 0.f;

#pragma unroll 1
        for (int it = 0; it < 32; it++) {
            int j = it*32 + lane;
            unsigned mw = __ldg(mrow + it);
            float e = fs + gd_s[j];
            e = e > 0.f ? e : 0.2f*e;
            float p = ((mw >> lane) & 1u) ? __expf(e) : 0.f;
            z += p;
            const float* v = &Vs[j*NP];       // 48B rows -> 16B aligned
            float4 v0 = *(const float4*)v;
            float4 v1 = *(const float4*)(v + 4);
            float4 v2 = *(const float4*)(v + 8);
            acc[0] += p*v0.x; acc[1] += p*v0.y; acc[2]  += p*v0.z; acc[3]  += p*v0.w;
            acc[4] += p*v1.x; acc[5] += p*v1.y; acc[6]  += p*v1.z; acc[7]  += p*v1.w;
            acc[8] += p*v2.x; acc[9] += p*v2.y; acc[10] += p*v2.z; acc[11] += p*v2.w;
        }
#pragma unroll
        for (int s = 16; s > 0; s >>= 1) {
            z += __shfl_xor_sync(0xffffffffu, z, s);
#pragma unroll
            for (int p = 0; p < NP; p++)
                acc[p] += __shfl_xor_sync(0xffffffffu, acc[p], s);
        }
        if (lane == 0) {
            float inv = 1.f / z;
#pragma unroll
            for (int p = 0; p < NP; p++) {
                float v = acc[p]*inv;
                v = v > 0.f ? v : (__expf(v) - 1.f);   // outer ELU
                out[(size_t)b*NN*NP + (size_t)i*NP + p] = v;
            }
        }
    }
}

// ---------------- launch ----------------
extern "C" void kernel_launch(void* const* d_in, const int* in_sizes, int n_in,
                              void* d_out, int out_size) {
    const float* x         = (const float*)d_in[0];
    const int*   adj       = (const int*)  d_in[1];
    const float* W         = (const float*)d_in[2];
    const float* a_src     = (const float*)d_in[3];
    const float* a_dst     = (const float*)d_in[4];
    const float* W_out     = (const float*)d_in[5];
    const float* a_out_src = (const float*)d_in[6];
    const float* a_out_dst = (const float*)d_in[7];
    float* out = (float*)d_out;

    int smem2 = (32*WT_STRIDE + NN + 16*256) * (int)sizeof(float);  // ~152 KB
    int smem4 = (NN*NP + NN) * (int)sizeof(float);                  // ~52 KB
    cudaFuncSetAttribute(k_attn1, cudaFuncAttributeMaxDynamicSharedMemorySize, smem2);
    cudaFuncSetAttribute(k_attn2, cudaFuncAttributeMaxDynamicSharedMemorySize, smem4);

    k_mask<<<NN, NN>>>(adj);
    k_wh<<<dim3(B*HEADS, NN/256), 256>>>(x, W, a_src, a_dst);
    k_attn1<<<B*HEADS*2, 512, smem2>>>();
    k_wh2<<<B*NN/256, 256>>>(W_out, a_out_src, a_out_dst);
    k_attn2<<<B*8, 512, smem4>>>(out);
}

// round 4
// speedup vs baseline: 2.0306x; 2.0306x over previous
#include <cuda_runtime.h>
#include <cstdint>

#define B 16
#define NN 1024
#define NF 16
#define NHID 32
#define HEADS 4
#define NP 12
#define LOG2E 1.4426950408889634f

__device__ float    g_Wh[B*HEADS*NN*NHID];
__device__ float    g_fsrc[B*HEADS*NN];
__device__ float    g_fdst[B*HEADS*NN];
__device__ unsigned g_mask[NN*NN/32];
__device__ float    g_h[B*NN*HEADS*NHID];
__device__ float    g_Wh2[B*NN*NP];
__device__ float    g_gsrc[B*NN];
__device__ float    g_gdst[B*NN];

__device__ __forceinline__ uint32_t to_tf32(float v) {
    uint32_t t; asm("cvt.rna.tf32.f32 %0, %1;" : "=r"(t) : "f"(v)); return t;
}
__device__ __forceinline__ float ex2f(float x) {
    float y; asm("ex2.approx.f32 %0, %1;" : "=f"(y) : "f"(x)); return y;
}
__device__ __forceinline__ float eluf(float v) { return v > 0.f ? v : (ex2f(v*LOG2E) - 1.f); }
__device__ __forceinline__ void mma8(float* d, uint32_t a0, uint32_t a1, uint32_t a2, uint32_t a3,
                                     uint32_t b0, uint32_t b1) {
    asm("mma.sync.aligned.m16n8k8.row.col.f32.tf32.tf32.f32 "
        "{%0,%1,%2,%3},{%4,%5,%6,%7},{%8,%9},{%0,%1,%2,%3};"
        : "+f"(d[0]), "+f"(d[1]), "+f"(d[2]), "+f"(d[3])
        : "r"(a0), "r"(a1), "r"(a2), "r"(a3), "r"(b0), "r"(b1));
}

// ---------------- K0: adjacency -> bitmask ----------------
__global__ void k_mask(const int* __restrict__ adj) {
    int i = blockIdx.x, j = threadIdx.x;
    unsigned bal = __ballot_sync(0xffffffffu, adj[i*NN + j] > 0);
    if ((j & 31) == 0) g_mask[i*32 + (j >> 5)] = bal;
}

// ---------------- K1: Wh = x@W, f_src/f_dst ----------------
__global__ void k_wh(const float* __restrict__ x, const float* __restrict__ W,
                     const float* __restrict__ a_src, const float* __restrict__ a_dst) {
    __shared__ float Ws[NF*NHID], as_s[NHID], ad_s[NHID];
    int bh = blockIdx.x, b = bh >> 2, h = bh & 3, tid = threadIdx.x;
    for (int i = tid; i < NF*NHID; i += 256) Ws[i] = W[h*NF*NHID + i];
    if (tid < NHID) { as_s[tid] = a_src[h*NHID + tid]; ad_s[tid] = a_dst[h*NHID + tid]; }
    __syncthreads();
    int n = blockIdx.y*256 + tid;
    const float4* xp = (const float4*)(x + ((size_t)b*NN + n)*NF);
    float xf[NF];
#pragma unroll
    for (int i = 0; i < NF/4; i++) {
        float4 v = __ldg(xp + i);
        xf[4*i] = v.x; xf[4*i+1] = v.y; xf[4*i+2] = v.z; xf[4*i+3] = v.w;
    }
    float wh[NHID];
#pragma unroll
    for (int k = 0; k < NHID; k++) wh[k] = 0.f;
#pragma unroll
    for (int f = 0; f < NF; f++) {
        float xv = xf[f];
#pragma unroll
        for (int k = 0; k < NHID; k++) wh[k] += xv * Ws[f*NHID + k];
    }
    float fs = 0.f, fd = 0.f;
#pragma unroll
    for (int k = 0; k < NHID; k++) { fs += wh[k]*as_s[k]; fd += wh[k]*ad_s[k]; }
    float* op = g_Wh + ((size_t)bh*NN + n)*NHID;
#pragma unroll
    for (int k = 0; k < NHID; k += 4)
        *(float4*)(op + k) = make_float4(wh[k], wh[k+1], wh[k+2], wh[k+3]);
    g_fsrc[bh*NN + n] = fs;
    g_fdst[bh*NN + n] = fd;
}

// ---------------- K2: tf32 mma.sync fused masked softmax + attn@Wh + ELU ----------------
// CTA = (b,h,half): 512 rows, 16 warps x 32 rows. j staged in 2 phases of 512.
// smem: WhHi/WhLo [32][512] tf32 (XOR-swizzled), fd_s[1024], fs_s[512] (x log2e).
__global__ void __launch_bounds__(512, 1) k_attn1_m() {
    extern __shared__ float sm[];
    uint32_t* WhHi = (uint32_t*)sm;            // 32*512
    uint32_t* WhLo = WhHi + 32*512;
    float* fd_s = sm + 64*512;                 // 1024
    float* fs_s = fd_s + 1024;                 // 512

    int tid = threadIdx.x, warp = tid >> 5, lane = tid & 31;
    int r = lane & 3, q = lane >> 2;
    int bh = blockIdx.x >> 1, half = blockIdx.x & 1;
    int b = bh >> 2, h = bh & 3, row0 = half*512;

    for (int i = tid; i < NN; i += 512) fd_s[i] = g_fdst[bh*NN + i] * LOG2E;
    fs_s[tid] = g_fsrc[bh*NN + row0 + tid] * LOG2E;

    const unsigned* mp[4];
#pragma unroll
    for (int t = 0; t < 4; t++)
        mp[t] = g_mask + (size_t)(row0 + warp*32 + q + 8*t)*32;

    float acc[2][4][4];
#pragma unroll
    for (int f = 0; f < 2; f++)
#pragma unroll
        for (int nt = 0; nt < 4; nt++)
#pragma unroll
            for (int i = 0; i < 4; i++) acc[f][nt][i] = 0.f;
    float z[4] = {0.f, 0.f, 0.f, 0.f};
    float fsv[4];

#pragma unroll 1
    for (int ph = 0; ph < 2; ph++) {
        int J0 = ph*512;
        __syncthreads();
        const float* Whg = g_Wh + ((size_t)bh*NN + J0)*NHID;
        for (int idx = tid; idx < 512*NHID; idx += 512) {
            int j = idx >> 5, k = idx & 31;
            float w = Whg[idx];
            uint32_t hi = to_tf32(w);
            uint32_t lo = to_tf32(w - __uint_as_float(hi));
            int jsw = j ^ ((k & 7) << 2);
            WhHi[k*512 + jsw] = hi;
            WhLo[k*512 + jsw] = lo;
        }
        __syncthreads();
#pragma unroll
        for (int t = 0; t < 4; t++) fsv[t] = fs_s[warp*32 + q + 8*t];

        int wbase = J0 >> 5;
        unsigned mw[4];
#pragma unroll
        for (int t = 0; t < 4; t++) mw[t] = __ldg(mp[t] + wbase);

#pragma unroll 1
        for (int g = 0; g < 16; g++) {
            unsigned mwn[4];
            if (g < 15) {
#pragma unroll
                for (int t = 0; t < 4; t++) mwn[t] = __ldg(mp[t] + wbase + g + 1);
            }
#pragma unroll
            for (int c = 0; c < 4; c++) {
                int j0 = g*32 + c*8;
                float fd0 = fd_s[J0 + j0 + r];
                float fd1 = fd_s[J0 + j0 + 4 + r];
                float p0[4], p1[4];
#pragma unroll
                for (int t = 0; t < 4; t++) {
                    float e0 = fsv[t] + fd0; e0 = fmaxf(e0, 0.2f*e0);
                    float e1 = fsv[t] + fd1; e1 = fmaxf(e1, 0.2f*e1);
                    float x0 = ex2f(e0), x1 = ex2f(e1);
                    p0[t] = ((mw[t] >> (c*8 + r)) & 1u) ? x0 : 0.f;
                    p1[t] = ((mw[t] >> (c*8 + 4 + r)) & 1u) ? x1 : 0.f;
                    z[t] += p0[t] + p1[t];
                }
                uint32_t phi0[4], plo0[4], phi1[4], plo1[4];
#pragma unroll
                for (int t = 0; t < 4; t++) {
                    phi0[t] = to_tf32(p0[t]);
                    plo0[t] = to_tf32(p0[t] - __uint_as_float(phi0[t]));
                    phi1[t] = to_tf32(p1[t]);
                    plo1[t] = to_tf32(p1[t] - __uint_as_float(phi1[t]));
                }
                int sw0 = (j0 + r) ^ (q << 2);
                int sw1 = (j0 + 4 + r) ^ (q << 2);
#pragma unroll
                for (int nt = 0; nt < 4; nt++) {
                    int kb = (nt*8 + q)*512;
                    uint32_t bh0 = WhHi[kb + sw0], bh1 = WhHi[kb + sw1];
                    uint32_t bl0 = WhLo[kb + sw0], bl1 = WhLo[kb + sw1];
#pragma unroll
                    for (int f = 0; f < 2; f++) {
                        mma8(acc[f][nt], phi0[2*f], phi0[2*f+1], phi1[2*f], phi1[2*f+1], bh0, bh1);
                        mma8(acc[f][nt], phi0[2*f], phi0[2*f+1], phi1[2*f], phi1[2*f+1], bl0, bl1);
                        mma8(acc[f][nt], plo0[2*f], plo0[2*f+1], plo1[2*f], plo1[2*f+1], bh0, bh1);
                    }
                }
            }
#pragma unroll
            for (int t = 0; t < 4; t++) mw[t] = mwn[t];
        }
    }

    float inv[4];
#pragma unroll
    for (int t = 0; t < 4; t++) {
        float zv = z[t];
        zv += __shfl_xor_sync(0xffffffffu, zv, 1);
        zv += __shfl_xor_sync(0xffffffffu, zv, 2);
        inv[t] = 1.f / zv;
    }
#pragma unroll
    for (int f = 0; f < 2; f++) {
        int node_lo = row0 + warp*32 + q + 16*f;
        float* base_lo = g_h + ((size_t)(b*NN + node_lo))*(HEADS*NHID) + h*NHID + 2*r;
        float* base_hi = base_lo + 8*(HEADS*NHID);
#pragma unroll
        for (int nt = 0; nt < 4; nt++) {
            float2 v0, v1;
            v0.x = eluf(acc[f][nt][0]*inv[2*f]);
            v0.y = eluf(acc[f][nt][1]*inv[2*f]);
            v1.x = eluf(acc[f][nt][2]*inv[2*f+1]);
            v1.y = eluf(acc[f][nt][3]*inv[2*f+1]);
            *(float2*)(base_lo + nt*8) = v0;
            *(float2*)(base_hi + nt*8) = v1;
        }
    }
}

// ---------------- K3: Wh2 = h@W_out (4-way split), g dots ----------------
__global__ void k_wh2(const float* __restrict__ W_out,
                      const float* __restrict__ ao_src, const float* __restrict__ ao_dst) {
    int gidx = blockIdx.x*256 + threadIdx.x;
    int bn = gidx >> 2, part = gidx & 3;
    const float* hp = g_h + (size_t)bn*128 + part*32;
    const float* wp = W_out + part*32*NP;
    float o[NP];
#pragma unroll
    for (int p = 0; p < NP; p++) o[p] = 0.f;
#pragma unroll
    for (int dq = 0; dq < 8; dq++) {
        float4 hv = __ldg((const float4*)hp + dq);
        float hh[4] = {hv.x, hv.y, hv.z, hv.w};
#pragma unroll
        for (int qq = 0; qq < 4; qq++) {
            const float4* wr = (const float4*)(wp + (dq*4 + qq)*NP);
            float4 w0 = __ldg(wr), w1 = __ldg(wr + 1), w2 = __ldg(wr + 2);
            float hx = hh[qq];
            o[0] += hx*w0.x; o[1] += hx*w0.y; o[2]  += hx*w0.z; o[3]  += hx*w0.w;
            o[4] += hx*w1.x; o[5] += hx*w1.y; o[6]  += hx*w1.z; o[7]  += hx*w1.w;
            o[8] += hx*w2.x; o[9] += hx*w2.y; o[10] += hx*w2.z; o[11] += hx*w2.w;
        }
    }
#pragma unroll
    for (int p = 0; p < NP; p++) {
        o[p] += __shfl_xor_sync(0xffffffffu, o[p], 1);
        o[p] += __shfl_xor_sync(0xffffffffu, o[p], 2);
    }
    if (part == 0) {
        float gs = 0.f, gd = 0.f;
#pragma unroll
        for (int p = 0; p < NP; p++) { gs += o[p]*__ldg(ao_src + p); gd += o[p]*__ldg(ao_dst + p); }
        float* op = g_Wh2 + (size_t)bn*NP;
#pragma unroll
        for (int p = 0; p < NP; p++) op[p] = o[p];
        g_gsrc[bn] = gs;
        g_gdst[bn] = gd;
    }
}

// ---------------- K4: layer-2 fused masked softmax + attn2@Wh2 + ELU ----------------
// 4 rows share each V load; exp2 domain.
__global__ void __launch_bounds__(512, 1) k_attn2(float* __restrict__ out) {
    extern __shared__ float sm[];
    float* Vs   = sm;              // 1024*12
    float* gd_s = sm + NN*NP;      // 1024
    int b = blockIdx.x >> 3, chunk = blockIdx.x & 7, tid = threadIdx.x;
    const float* Vg = g_Wh2 + (size_t)b*NN*NP;
    for (int i = tid; i < NN*NP; i += 512) Vs[i] = Vg[i];
    for (int i = tid; i < NN; i += 512) gd_s[i] = g_gdst[b*NN + i] * LOG2E;
    __syncthreads();
    int warp = tid >> 5, lane = tid & 31;
#pragma unroll 1
    for (int g = 0; g < 2; g++) {
        int ibase = chunk*128 + warp*8 + g*4;
        float fs[4];
        const unsigned* mp[4];
#pragma unroll
        for (int t = 0; t < 4; t++) {
            fs[t] = g_gsrc[b*NN + ibase + t] * LOG2E;
            mp[t] = g_mask + (size_t)(ibase + t)*32;
        }
        float z[4] = {0.f, 0.f, 0.f, 0.f};
        float acc[4][NP];
#pragma unroll
        for (int t = 0; t < 4; t++)
#pragma unroll
            for (int p = 0; p < NP; p++) acc[t][p] = 0.f;

#pragma unroll 1
        for (int it = 0; it < 32; it++) {
            int j = it*32 + lane;
            float gd = gd_s[j];
            const float* v = &Vs[j*NP];
            float4 v0 = *(const float4*)v;
            float4 v1 = *(const float4*)(v + 4);
            float4 v2 = *(const float4*)(v + 8);
#pragma unroll
            for (int t = 0; t < 4; t++) {
                unsigned mwv = __ldg(mp[t] + it);
                float e = fs[t] + gd; e = fmaxf(e, 0.2f*e);
                float p = ((mwv >> lane) & 1u) ? ex2f(e) : 0.f;
                z[t] += p;
                acc[t][0] += p*v0.x; acc[t][1] += p*v0.y; acc[t][2]  += p*v0.z; acc[t][3]  += p*v0.w;
                acc[t][4] += p*v1.x; acc[t][5] += p*v1.y; acc[t][6]  += p*v1.z; acc[t][7]  += p*v1.w;
                acc[t][8] += p*v2.x; acc[t][9] += p*v2.y; acc[t][10] += p*v2.z; acc[t][11] += p*v2.w;
            }
        }
#pragma unroll
        for (int t = 0; t < 4; t++) {
#pragma unroll
            for (int s = 16; s > 0; s >>= 1) {
                z[t] += __shfl_xor_sync(0xffffffffu, z[t], s);
#pragma unroll
                for (int p = 0; p < NP; p++)
                    acc[t][p] += __shfl_xor_sync(0xffffffffu, acc[t][p], s);
            }
            if (lane == 0) {
                float invz = 1.f / z[t];
#pragma unroll
                for (int p = 0; p < NP; p++)
                    out[(size_t)b*NN*NP + (size_t)(ibase + t)*NP + p] = eluf(acc[t][p]*invz);
            }
        }
    }
}

// ---------------- launch ----------------
extern "C" void kernel_launch(void* const* d_in, const int* in_sizes, int n_in,
                              void* d_out, int out_size) {
    const float* x         = (const float*)d_in[0];
    const int*   adj       = (const int*)  d_in[1];
    const float* W         = (const float*)d_in[2];
    const float* a_src     = (const float*)d_in[3];
    const float* a_dst     = (const float*)d_in[4];
    const float* W_out     = (const float*)d_in[5];
    const float* a_out_src = (const float*)d_in[6];
    const float* a_out_dst = (const float*)d_in[7];
    float* out = (float*)d_out;

    int smem1 = (64*512 + NN + 512) * (int)sizeof(float);   // 137216 B
    int smem4 = (NN*NP + NN) * (int)sizeof(float);          // 53248 B
    cudaFuncSetAttribute(k_attn1_m, cudaFuncAttributeMaxDynamicSharedMemorySize, smem1);
    cudaFuncSetAttribute(k_attn2,   cudaFuncAttributeMaxDynamicSharedMemorySize, smem4);

    k_mask<<<NN, NN>>>(adj);
    k_wh<<<dim3(B*HEADS, NN/256), 256>>>(x, W, a_src, a_dst);
    k_attn1_m<<<B*HEADS*2, 512, smem1>>>();
    k_wh2<<<B*NN*4/256, 256>>>(W_out, a_out_src, a_out_dst);
    k_attn2<<<B*8, 512, smem4>>>(out);
}

// round 5
// speedup vs baseline: 2.4727x; 1.2177x over previous
#include <cuda_runtime.h>
#include <cstdint>

#define B 16
#define NN 1024
#define NF 16
#define NHID 32
#define HEADS 4
#define NP 12
#define LOG2E 1.4426950408889634f

__device__ float    g_Wh[B*HEADS*NN*NHID];
__device__ float    g_fsrc[B*HEADS*NN];
__device__ float    g_fdst[B*HEADS*NN];
__device__ unsigned g_mask[NN*NN/32];
__device__ float    g_h[B*NN*HEADS*NHID];
__device__ float    g_Wh2[B*NN*NP];
__device__ float    g_gsrc[B*NN];
__device__ float    g_gdst[B*NN];

__device__ __forceinline__ float ex2f(float x) {
    float y; asm("ex2.approx.f32 %0, %1;" : "=f"(y) : "f"(x)); return y;
}
__device__ __forceinline__ float eluf(float v) { return v > 0.f ? v : (ex2f(v*LOG2E) - 1.f); }

// pack (a->low, b->high) to bf16x2, plus residual pair for error compensation
__device__ __forceinline__ void pksplit(float a, float b, uint32_t& hi, uint32_t& lo) {
    uint32_t h;
    asm("cvt.rn.bf16x2.f32 %0, %1, %2;" : "=r"(h) : "f"(b), "f"(a));
    float ha = __uint_as_float(h << 16);
    float hb = __uint_as_float(h & 0xffff0000u);
    asm("cvt.rn.bf16x2.f32 %0, %1, %2;" : "=r"(lo) : "f"(b - hb), "f"(a - ha));
    hi = h;
}
__device__ __forceinline__ void mma16(float* d, const uint32_t* a, uint32_t b0, uint32_t b1) {
    asm("mma.sync.aligned.m16n8k16.row.col.f32.bf16.bf16.f32 "
        "{%0,%1,%2,%3},{%4,%5,%6,%7},{%8,%9},{%0,%1,%2,%3};"
        : "+f"(d[0]), "+f"(d[1]), "+f"(d[2]), "+f"(d[3])
        : "r"(a[0]), "r"(a[1]), "r"(a[2]), "r"(a[3]), "r"(b0), "r"(b1));
}

// ---------------- K0: adjacency -> bitmask ----------------
__global__ void k_mask(const int* __restrict__ adj) {
    int i = blockIdx.x, j = threadIdx.x;
    unsigned bal = __ballot_sync(0xffffffffu, adj[i*NN + j] > 0);
    if ((j & 31) == 0) g_mask[i*32 + (j >> 5)] = bal;
}

// ---------------- K1: Wh = x@W, f_src/f_dst ----------------
__global__ void k_wh(const float* __restrict__ x, const float* __restrict__ W,
                     const float* __restrict__ a_src, const float* __restrict__ a_dst) {
    __shared__ float Ws[NF*NHID], as_s[NHID], ad_s[NHID];
    int bh = blockIdx.x, b = bh >> 2, h = bh & 3, tid = threadIdx.x;
    for (int i = tid; i < NF*NHID; i += 256) Ws[i] = W[h*NF*NHID + i];
    if (tid < NHID) { as_s[tid] = a_src[h*NHID + tid]; ad_s[tid] = a_dst[h*NHID + tid]; }
    __syncthreads();
    int n = blockIdx.y*256 + tid;
    const float4* xp = (const float4*)(x + ((size_t)b*NN + n)*NF);
    float xf[NF];
#pragma unroll
    for (int i = 0; i < NF/4; i++) {
        float4 v = __ldg(xp + i);
        xf[4*i] = v.x; xf[4*i+1] = v.y; xf[4*i+2] = v.z; xf[4*i+3] = v.w;
    }
    float wh[NHID];
#pragma unroll
    for (int k = 0; k < NHID; k++) wh[k] = 0.f;
#pragma unroll
    for (int f = 0; f < NF; f++) {
        float xv = xf[f];
#pragma unroll
        for (int k = 0; k < NHID; k++) wh[k] += xv * Ws[f*NHID + k];
    }
    float fs = 0.f, fd = 0.f;
#pragma unroll
    for (int k = 0; k < NHID; k++) { fs += wh[k]*as_s[k]; fd += wh[k]*ad_s[k]; }
    float* op = g_Wh + ((size_t)bh*NN + n)*NHID;
#pragma unroll
    for (int k = 0; k < NHID; k += 4)
        *(float4*)(op + k) = make_float4(wh[k], wh[k+1], wh[k+2], wh[k+3]);
    g_fsrc[bh*NN + n] = fs;
    g_fdst[bh*NN + n] = fd;
}

// ---------------- K2: bf16 m16n8k16 (3-term compensated) fused GAT layer 1 ----------------
// CTA = (b,h,half): 512 rows, 16 warps x 32 rows. Full 1024-j WhT staged once as
// bf16x2 hi/lo pairs: WhHi/WhLo[k][512 j-pairs], XOR-swizzled (jp ^ (q<<2)).
__global__ void __launch_bounds__(512, 1) k_attn1_b() {
    extern __shared__ float sm[];
    uint32_t* WhHi = (uint32_t*)sm;              // 32*512 u32
    uint32_t* WhLo = WhHi + 32*512;
    float* fd_s = (float*)(WhLo + 32*512);       // 1024
    float* fs_s = fd_s + NN;                     // 512

    int tid = threadIdx.x, warp = tid >> 5, lane = tid & 31;
    int r = lane & 3, q = lane >> 2;
    int bh = blockIdx.x >> 1, half = blockIdx.x & 1;
    int b = bh >> 2, h = bh & 3, row0 = half*512;

    // stage: Wh[j][k] -> packed pairs (j even/odd) split hi/lo
    const float* Whg = g_Wh + (size_t)bh*NN*NHID;
    for (int idx = tid; idx < NN*NHID/2; idx += 512) {
        int jp = idx >> 5, k = idx & 31;
        float w0 = Whg[(2*jp)*NHID + k];
        float w1 = Whg[(2*jp+1)*NHID + k];
        uint32_t hi, lo;
        pksplit(w0, w1, hi, lo);
        int jsw = jp ^ ((k & 7) << 2);
        WhHi[k*512 + jsw] = hi;
        WhLo[k*512 + jsw] = lo;
    }
    for (int i = tid; i < NN; i += 512) fd_s[i] = g_fdst[bh*NN + i] * LOG2E;
    fs_s[tid] = g_fsrc[bh*NN + row0 + tid] * LOG2E;
    __syncthreads();

    const unsigned* mp[4];
    float fsv[4];
#pragma unroll
    for (int t = 0; t < 4; t++) {
        mp[t] = g_mask + (size_t)(row0 + warp*32 + q + 8*t)*32;
        fsv[t] = fs_s[warp*32 + q + 8*t];
    }

    float acc[2][4][4];
#pragma unroll
    for (int f = 0; f < 2; f++)
#pragma unroll
        for (int nt = 0; nt < 4; nt++)
#pragma unroll
            for (int i = 0; i < 4; i++) acc[f][nt][i] = 0.f;
    float z[4] = {0.f, 0.f, 0.f, 0.f};

    unsigned mw[4], mwn[4];
#pragma unroll
    for (int t = 0; t < 4; t++) mw[t] = __ldg(mp[t]);

#pragma unroll 1
    for (int g = 0; g < 32; g++) {
        if (g < 31) {
#pragma unroll
            for (int t = 0; t < 4; t++) mwn[t] = __ldg(mp[t] + g + 1);
        }
#pragma unroll
        for (int ck = 0; ck < 2; ck++) {
            int j0 = g*32 + ck*16;
            float2 fdA = *(const float2*)&fd_s[j0 + 2*r];
            float2 fdB = *(const float2*)&fd_s[j0 + 2*r + 8];
            uint32_t Ahi[2][4], Alo[2][4];
#pragma unroll
            for (int f = 0; f < 2; f++) {
#pragma unroll
                for (int hh = 0; hh < 2; hh++) {
                    int t = 2*f + hh;                          // row q + 8t
                    unsigned m = mw[t] >> (ck*16 + 2*r);
                    float fsr = fsv[t];
                    float e0 = fsr + fdA.x; e0 = fmaxf(e0, 0.2f*e0);
                    float e1 = fsr + fdA.y; e1 = fmaxf(e1, 0.2f*e1);
                    float e8 = fsr + fdB.x; e8 = fmaxf(e8, 0.2f*e8);
                    float e9 = fsr + fdB.y; e9 = fmaxf(e9, 0.2f*e9);
                    float p0 = (m & 1u)        ? ex2f(e0) : 0.f;
                    float p1 = (m & 2u)        ? ex2f(e1) : 0.f;
                    float p8 = ((m >> 8) & 1u) ? ex2f(e8) : 0.f;
                    float p9 = ((m >> 9) & 1u) ? ex2f(e9) : 0.f;
                    z[t] += (p0 + p1) + (p8 + p9);
                    pksplit(p0, p1, Ahi[f][hh],     Alo[f][hh]);      // a0 / a1
                    pksplit(p8, p9, Ahi[f][2 + hh], Alo[f][2 + hh]);  // a2 / a3
                }
            }
            int jp0 = g*16 + ck*8;
            int sw0 = (jp0 + r)     ^ (q << 2);
            int sw1 = (jp0 + 4 + r) ^ (q << 2);
#pragma unroll
            for (int nt = 0; nt < 4; nt++) {
                int base = (nt*8 + q) * 512;
                uint32_t bh0 = WhHi[base + sw0], bh1 = WhHi[base + sw1];
                uint32_t bl0 = WhLo[base + sw0], bl1 = WhLo[base + sw1];
#pragma unroll
                for (int f = 0; f < 2; f++) {
                    mma16(acc[f][nt], Ahi[f], bh0, bh1);
                    mma16(acc[f][nt], Ahi[f], bl0, bl1);
                    mma16(acc[f][nt], Alo[f], bh0, bh1);
                }
            }
        }
#pragma unroll
        for (int t = 0; t < 4; t++) mw[t] = mwn[t];
    }

    float inv[4];
#pragma unroll
    for (int t = 0; t < 4; t++) {
        float zv = z[t];
        zv += __shfl_xor_sync(0xffffffffu, zv, 1);
        zv += __shfl_xor_sync(0xffffffffu, zv, 2);
        inv[t] = 1.f / zv;
    }
#pragma unroll
    for (int f = 0; f < 2; f++) {
        int node_lo = row0 + warp*32 + q + 16*f;
        float* base_lo = g_h + ((size_t)(b*NN + node_lo))*(HEADS*NHID) + h*NHID + 2*r;
        float* base_hi = base_lo + 8*(HEADS*NHID);
#pragma unroll
        for (int nt = 0; nt < 4; nt++) {
            float2 v0, v1;
            v0.x = eluf(acc[f][nt][0]*inv[2*f]);
            v0.y = eluf(acc[f][nt][1]*inv[2*f]);
            v1.x = eluf(acc[f][nt][2]*inv[2*f+1]);
            v1.y = eluf(acc[f][nt][3]*inv[2*f+1]);
            *(float2*)(base_lo + nt*8) = v0;
            *(float2*)(base_hi + nt*8) = v1;
        }
    }
}

// ---------------- K3: Wh2 = h@W_out (4-way split, W_out in smem), g dots ----------------
__global__ void k_wh2(const float* __restrict__ W_out,
                      const float* __restrict__ ao_src, const float* __restrict__ ao_dst) {
    __shared__ float Wo[128*NP];
    int tid = threadIdx.x;
    for (int i = tid; i < 128*NP; i += 256) Wo[i] = W_out[i];
    __syncthreads();
    int gidx = blockIdx.x*256 + tid;
    int bn = gidx >> 2, part = gidx & 3;
    const float* hp = g_h + (size_t)bn*128 + part*32;
    const float* wp = Wo + part*32*NP;
    float o[NP];
#pragma unroll
    for (int p = 0; p < NP; p++) o[p] = 0.f;
#pragma unroll
    for (int dq = 0; dq < 8; dq++) {
        float4 hv = __ldg((const float4*)hp + dq);
        float hh[4] = {hv.x, hv.y, hv.z, hv.w};
#pragma unroll
        for (int qq = 0; qq < 4; qq++) {
            const float4* wr = (const float4*)(wp + (dq*4 + qq)*NP);
            float4 w0 = wr[0], w1 = wr[1], w2 = wr[2];
            float hx = hh[qq];
            o[0] += hx*w0.x; o[1] += hx*w0.y; o[2]  += hx*w0.z; o[3]  += hx*w0.w;
            o[4] += hx*w1.x; o[5] += hx*w1.y; o[6]  += hx*w1.z; o[7]  += hx*w1.w;
            o[8] += hx*w2.x; o[9] += hx*w2.y; o[10] += hx*w2.z; o[11] += hx*w2.w;
        }
    }
#pragma unroll
    for (int p = 0; p < NP; p++) {
        o[p] += __shfl_xor_sync(0xffffffffu, o[p], 1);
        o[p] += __shfl_xor_sync(0xffffffffu, o[p], 2);
    }
    if (part == 0) {
        float gs = 0.f, gd = 0.f;
#pragma unroll
        for (int p = 0; p < NP; p++) { gs += o[p]*__ldg(ao_src + p); gd += o[p]*__ldg(ao_dst + p); }
        float* op = g_Wh2 + (size_t)bn*NP;
#pragma unroll
        for (int p = 0; p < NP; p++) op[p] = o[p];
        g_gsrc[bn] = gs;
        g_gdst[bn] = gd;
    }
}

// ---------------- K4: layer-2 fused masked softmax + attn2@Wh2 + ELU ----------------
__global__ void __launch_bounds__(512, 1) k_attn2(float* __restrict__ out) {
    extern __shared__ float sm[];
    float* Vs   = sm;
    float* gd_s = sm + NN*NP;
    int b = blockIdx.x >> 3, chunk = blockIdx.x & 7, tid = threadIdx.x;
    const float* Vg = g_Wh2 + (size_t)b*NN*NP;
    for (int i = tid; i < NN*NP; i += 512) Vs[i] = Vg[i];
    for (int i = tid; i < NN; i += 512) gd_s[i] = g_gdst[b*NN + i] * LOG2E;
    __syncthreads();
    int warp = tid >> 5, lane = tid & 31;
#pragma unroll 1
    for (int g = 0; g < 2; g++) {
        int ibase = chunk*128 + warp*8 + g*4;
        float fs[4];
        const unsigned* mp[4];
#pragma unroll
        for (int t = 0; t < 4; t++) {
            fs[t] = g_gsrc[b*NN + ibase + t] * LOG2E;
            mp[t] = g_mask + (size_t)(ibase + t)*32;
        }
        float z[4] = {0.f, 0.f, 0.f, 0.f};
        float acc[4][NP];
#pragma unroll
        for (int t = 0; t < 4; t++)
#pragma unroll
            for (int p = 0; p < NP; p++) acc[t][p] = 0.f;

#pragma unroll 1
        for (int it = 0; it < 32; it++) {
            int j = it*32 + lane;
            float gd = gd_s[j];
            const float* v = &Vs[j*NP];
            float4 v0 = *(const float4*)v;
            float4 v1 = *(const float4*)(v + 4);
            float4 v2 = *(const float4*)(v + 8);
#pragma unroll
            for (int t = 0; t < 4; t++) {
                unsigned mwv = __ldg(mp[t] + it);
                float e = fs[t] + gd; e = fmaxf(e, 0.2f*e);
                float p = ((mwv >> lane) & 1u) ? ex2f(e) : 0.f;
                z[t] += p;
                acc[t][0] += p*v0.x; acc[t][1] += p*v0.y; acc[t][2]  += p*v0.z; acc[t][3]  += p*v0.w;
                acc[t][4] += p*v1.x; acc[t][5] += p*v1.y; acc[t][6]  += p*v1.z; acc[t][7]  += p*v1.w;
                acc[t][8] += p*v2.x; acc[t][9] += p*v2.y; acc[t][10] += p*v2.z; acc[t][11] += p*v2.w;
            }
        }
#pragma unroll
        for (int t = 0; t < 4; t++) {
#pragma unroll
            for (int s = 16; s > 0; s >>= 1) {
                z[t] += __shfl_xor_sync(0xffffffffu, z[t], s);
#pragma unroll
                for (int p = 0; p < NP; p++)
                    acc[t][p] += __shfl_xor_sync(0xffffffffu, acc[t][p], s);
            }
            if (lane == 0) {
                float invz = 1.f / z[t];
#pragma unroll
                for (int p = 0; p < NP; p++)
                    out[(size_t)b*NN*NP + (size_t)(ibase + t)*NP + p] = eluf(acc[t][p]*invz);
            }
        }
    }
}

// ---------------- launch ----------------
extern "C" void kernel_launch(void* const* d_in, const int* in_sizes, int n_in,
                              void* d_out, int out_size) {
    const float* x         = (const float*)d_in[0];
    const int*   adj       = (const int*)  d_in[1];
    const float* W         = (const float*)d_in[2];
    const float* a_src     = (const float*)d_in[3];
    const float* a_dst     = (const float*)d_in[4];
    const float* W_out     = (const float*)d_in[5];
    const float* a_out_src = (const float*)d_in[6];
    const float* a_out_dst = (const float*)d_in[7];
    float* out = (float*)d_out;

    int smem1 = (32*512*2 + NN + 512) * (int)sizeof(float);  // 137216 B
    int smem4 = (NN*NP + NN) * (int)sizeof(float);           // 53248 B
    cudaFuncSetAttribute(k_attn1_b, cudaFuncAttributeMaxDynamicSharedMemorySize, smem1);
    cudaFuncSetAttribute(k_attn2,   cudaFuncAttributeMaxDynamicSharedMemorySize, smem4);

    k_mask<<<NN, NN>>>(adj);
    k_wh<<<dim3(B*HEADS, NN/256), 256>>>(x, W, a_src, a_dst);
    k_attn1_b<<<B*HEADS*2, 512, smem1>>>();
    k_wh2<<<B*NN*4/256, 256>>>(W_out, a_out_src, a_out_dst);
    k_attn2<<<B*8, 512, smem4>>>(out);
}

// round 6
// speedup vs baseline: 2.7312x; 1.1045x over previous
#include <cuda_runtime.h>
#include <cstdint>

#define B 16
#define NN 1024
#define NF 16
#define NHID 32
#define HEADS 4
#define NP 12
#define LOG2E 1.4426950408889634f

__device__ float    g_Wh[B*HEADS*NN*NHID];
__device__ float    g_fsrc[B*HEADS*NN];
__device__ float    g_fdst[B*HEADS*NN];
__device__ unsigned g_mask[NN*NN/32];
__device__ float    g_h[B*NN*HEADS*NHID];
__device__ float    g_Wh2[B*NN*NP];
__device__ float    g_gsrc[B*NN];
__device__ float    g_gdst[B*NN];

__device__ __forceinline__ float ex2f(float x) {
    float y; asm("ex2.approx.f32 %0, %1;" : "=f"(y) : "f"(x)); return y;
}
__device__ __forceinline__ float eluf(float v) { return v > 0.f ? v : (ex2f(v*LOG2E) - 1.f); }

__device__ __forceinline__ unsigned long long ffma2(unsigned long long a, unsigned long long b,
                                                    unsigned long long c) {
    unsigned long long d;
    asm("fma.rn.f32x2 %0, %1, %2, %3;" : "=l"(d) : "l"(a), "l"(b), "l"(c));
    return d;
}
__device__ __forceinline__ unsigned long long addf2(unsigned long long a, unsigned long long b) {
    unsigned long long d;
    asm("add.rn.f32x2 %0, %1, %2;" : "=l"(d) : "l"(a), "l"(b));
    return d;
}
__device__ __forceinline__ unsigned long long pack2(float x) {
    unsigned long long d;
    asm("mov.b64 %0, {%1, %2};" : "=l"(d) : "f"(x), "f"(x));
    return d;
}
__device__ __forceinline__ float2 unpk2(unsigned long long v) {
    float2 f;
    asm("mov.b64 {%0, %1}, %2;" : "=f"(f.x), "=f"(f.y) : "l"(v));
    return f;
}

// pack (a->low, b->high) to bf16x2, plus residual pair for error compensation
__device__ __forceinline__ void pksplit(float a, float b, uint32_t& hi, uint32_t& lo) {
    uint32_t h;
    asm("cvt.rn.bf16x2.f32 %0, %1, %2;" : "=r"(h) : "f"(b), "f"(a));
    float ha = __uint_as_float(h << 16);
    float hb = __uint_as_float(h & 0xffff0000u);
    asm("cvt.rn.bf16x2.f32 %0, %1, %2;" : "=r"(lo) : "f"(b - hb), "f"(a - ha));
    hi = h;
}
__device__ __forceinline__ void mma16(float* d, const uint32_t* a, uint32_t b0, uint32_t b1) {
    asm("mma.sync.aligned.m16n8k16.row.col.f32.bf16.bf16.f32 "
        "{%0,%1,%2,%3},{%4,%5,%6,%7},{%8,%9},{%0,%1,%2,%3};"
        : "+f"(d[0]), "+f"(d[1]), "+f"(d[2]), "+f"(d[3])
        : "r"(a[0]), "r"(a[1]), "r"(a[2]), "r"(a[3]), "r"(b0), "r"(b1));
}

// ---------------- K0a/K0b: adjacency -> bitmask (split so k_attn1 is launch #4) ----------------
__global__ void k_maskA(const int* __restrict__ adj) {
    int i = blockIdx.x, j = threadIdx.x;
    unsigned bal = __ballot_sync(0xffffffffu, adj[i*NN + j] > 0);
    if ((j & 31) == 0) g_mask[i*32 + (j >> 5)] = bal;
}
__global__ void k_maskB(const int* __restrict__ adj) {
    int i = blockIdx.x + NN/2, j = threadIdx.x;
    unsigned bal = __ballot_sync(0xffffffffu, adj[i*NN + j] > 0);
    if ((j & 31) == 0) g_mask[i*32 + (j >> 5)] = bal;
}

// ---------------- K1: Wh = x@W, f_src/f_dst ----------------
__global__ void k_wh(const float* __restrict__ x, const float* __restrict__ W,
                     const float* __restrict__ a_src, const float* __restrict__ a_dst) {
    __shared__ float Ws[NF*NHID], as_s[NHID], ad_s[NHID];
    int bh = blockIdx.x, b = bh >> 2, h = bh & 3, tid = threadIdx.x;
    for (int i = tid; i < NF*NHID; i += 256) Ws[i] = W[h*NF*NHID + i];
    if (tid < NHID) { as_s[tid] = a_src[h*NHID + tid]; ad_s[tid] = a_dst[h*NHID + tid]; }
    __syncthreads();
    int n = blockIdx.y*256 + tid;
    const float4* xp = (const float4*)(x + ((size_t)b*NN + n)*NF);
    float xf[NF];
#pragma unroll
    for (int i = 0; i < NF/4; i++) {
        float4 v = __ldg(xp + i);
        xf[4*i] = v.x; xf[4*i+1] = v.y; xf[4*i+2] = v.z; xf[4*i+3] = v.w;
    }
    float wh[NHID];
#pragma unroll
    for (int k = 0; k < NHID; k++) wh[k] = 0.f;
#pragma unroll
    for (int f = 0; f < NF; f++) {
        float xv = xf[f];
#pragma unroll
        for (int k = 0; k < NHID; k++) wh[k] += xv * Ws[f*NHID + k];
    }
    float fs = 0.f, fd = 0.f;
#pragma unroll
    for (int k = 0; k < NHID; k++) { fs += wh[k]*as_s[k]; fd += wh[k]*ad_s[k]; }
    float* op = g_Wh + ((size_t)bh*NN + n)*NHID;
#pragma unroll
    for (int k = 0; k < NHID; k += 4)
        *(float4*)(op + k) = make_float4(wh[k], wh[k+1], wh[k+2], wh[k+3]);
    g_fsrc[bh*NN + n] = fs;
    g_fdst[bh*NN + n] = fd;
}

// ---------------- K2: bf16 m16n8k16 (3-term compensated) fused GAT layer 1 ----------------
__global__ void __launch_bounds__(512, 1) k_attn1_b() {
    extern __shared__ float sm[];
    uint32_t* WhHi = (uint32_t*)sm;              // 32*512 u32
    uint32_t* WhLo = WhHi + 32*512;
    float* fd_s = (float*)(WhLo + 32*512);       // 1024
    float* fs_s = fd_s + NN;                     // 512

    int tid = threadIdx.x, warp = tid >> 5, lane = tid & 31;
    int r = lane & 3, q = lane >> 2;
    int bh = blockIdx.x >> 1, half = blockIdx.x & 1;
    int b = bh >> 2, h = bh & 3, row0 = half*512;

    const float* Whg = g_Wh + (size_t)bh*NN*NHID;
    for (int idx = tid; idx < NN*NHID/2; idx += 512) {
        int jp = idx >> 5, k = idx & 31;
        float w0 = Whg[(2*jp)*NHID + k];
        float w1 = Whg[(2*jp+1)*NHID + k];
        uint32_t hi, lo;
        pksplit(w0, w1, hi, lo);
        int jsw = jp ^ ((k & 7) << 2);
        WhHi[k*512 + jsw] = hi;
        WhLo[k*512 + jsw] = lo;
    }
    for (int i = tid; i < NN; i += 512) fd_s[i] = g_fdst[bh*NN + i] * LOG2E;
    fs_s[tid] = g_fsrc[bh*NN + row0 + tid] * LOG2E;
    __syncthreads();

    const unsigned* mp[4];
    float fsv[4];
#pragma unroll
    for (int t = 0; t < 4; t++) {
        mp[t] = g_mask + (size_t)(row0 + warp*32 + q + 8*t)*32;
        fsv[t] = fs_s[warp*32 + q + 8*t];
    }

    float acc[2][4][4];
#pragma unroll
    for (int f = 0; f < 2; f++)
#pragma unroll
        for (int nt = 0; nt < 4; nt++)
#pragma unroll
            for (int i = 0; i < 4; i++) acc[f][nt][i] = 0.f;
    float z[4] = {0.f, 0.f, 0.f, 0.f};

    unsigned mw[4], mwn[4];
#pragma unroll
    for (int t = 0; t < 4; t++) mw[t] = __ldg(mp[t]);

#pragma unroll 1
    for (int g = 0; g < 32; g++) {
        if (g < 31) {
#pragma unroll
            for (int t = 0; t < 4; t++) mwn[t] = __ldg(mp[t] + g + 1);
        }
#pragma unroll
        for (int ck = 0; ck < 2; ck++) {
            int j0 = g*32 + ck*16;
            float2 fdA = *(const float2*)&fd_s[j0 + 2*r];
            float2 fdB = *(const float2*)&fd_s[j0 + 2*r + 8];
            uint32_t Ahi[2][4], Alo[2][4];
#pragma unroll
            for (int f = 0; f < 2; f++) {
#pragma unroll
                for (int hh = 0; hh < 2; hh++) {
                    int t = 2*f + hh;
                    unsigned m = mw[t] >> (ck*16 + 2*r);
                    float fsr = fsv[t];
                    float e0 = fsr + fdA.x; e0 = fmaxf(e0, 0.2f*e0);
                    float e1 = fsr + fdA.y; e1 = fmaxf(e1, 0.2f*e1);
                    float e8 = fsr + fdB.x; e8 = fmaxf(e8, 0.2f*e8);
                    float e9 = fsr + fdB.y; e9 = fmaxf(e9, 0.2f*e9);
                    float p0 = (m & 1u)        ? ex2f(e0) : 0.f;
                    float p1 = (m & 2u)        ? ex2f(e1) : 0.f;
                    float p8 = ((m >> 8) & 1u) ? ex2f(e8) : 0.f;
                    float p9 = ((m >> 9) & 1u) ? ex2f(e9) : 0.f;
                    z[t] += (p0 + p1) + (p8 + p9);
                    pksplit(p0, p1, Ahi[f][hh],     Alo[f][hh]);
                    pksplit(p8, p9, Ahi[f][2 + hh], Alo[f][2 + hh]);
                }
            }
            int jp0 = g*16 + ck*8;
            int sw0 = (jp0 + r)     ^ (q << 2);
            int sw1 = (jp0 + 4 + r) ^ (q << 2);
#pragma unroll
            for (int nt = 0; nt < 4; nt++) {
                int base = (nt*8 + q) * 512;
                uint32_t bh0 = WhHi[base + sw0], bh1 = WhHi[base + sw1];
                uint32_t bl0 = WhLo[base + sw0], bl1 = WhLo[base + sw1];
#pragma unroll
                for (int f = 0; f < 2; f++) {
                    mma16(acc[f][nt], Ahi[f], bh0, bh1);
                    mma16(acc[f][nt], Ahi[f], bl0, bl1);
                    mma16(acc[f][nt], Alo[f], bh0, bh1);
                }
            }
        }
#pragma unroll
        for (int t = 0; t < 4; t++) mw[t] = mwn[t];
    }

    float inv[4];
#pragma unroll
    for (int t = 0; t < 4; t++) {
        float zv = z[t];
        zv += __shfl_xor_sync(0xffffffffu, zv, 1);
        zv += __shfl_xor_sync(0xffffffffu, zv, 2);
        inv[t] = 1.f / zv;
    }
#pragma unroll
    for (int f = 0; f < 2; f++) {
        int node_lo = row0 + warp*32 + q + 16*f;
        float* base_lo = g_h + ((size_t)(b*NN + node_lo))*(HEADS*NHID) + h*NHID + 2*r;
        float* base_hi = base_lo + 8*(HEADS*NHID);
#pragma unroll
        for (int nt = 0; nt < 4; nt++) {
            float2 v0, v1;
            v0.x = eluf(acc[f][nt][0]*inv[2*f]);
            v0.y = eluf(acc[f][nt][1]*inv[2*f]);
            v1.x = eluf(acc[f][nt][2]*inv[2*f+1]);
            v1.y = eluf(acc[f][nt][3]*inv[2*f+1]);
            *(float2*)(base_lo + nt*8) = v0;
            *(float2*)(base_hi + nt*8) = v1;
        }
    }
}

// ---------------- K3: Wh2 = h@W_out (4-way split, f32x2, rotated conflict-free W) ----------------
__global__ void k_wh2(const float* __restrict__ W_out,
                      const float* __restrict__ ao_src, const float* __restrict__ ao_dst) {
    __shared__ float Wo[128*NP];
    int tid = threadIdx.x;
    for (int i = tid; i < 128*NP; i += 256) Wo[i] = W_out[i];
    __syncthreads();
    int gidx = blockIdx.x*256 + tid;
    int bn = gidx >> 2, part = gidx & 3;
    const float4* hp4 = (const float4*)(g_h + (size_t)bn*128 + part*32);
    unsigned long long o2[6];
#pragma unroll
    for (int i = 0; i < 6; i++) o2[i] = 0ull;
#pragma unroll
    for (int dq = 0; dq < 8; dq++) {
        float4 hv = __ldg(hp4 + dq);
        float hh[4] = {hv.x, hv.y, hv.z, hv.w};
#pragma unroll
        for (int qq = 0; qq < 4; qq++) {
            int qr = (qq + part) & 3;                       // rotate -> conflict-free banks
            int row = part*32 + dq*4 + qr;
            unsigned long long hx2 = pack2(hh[qr]);
            const unsigned long long* wr = (const unsigned long long*)(Wo + row*NP);
#pragma unroll
            for (int i = 0; i < 6; i++) o2[i] = ffma2(hx2, wr[i], o2[i]);
        }
    }
#pragma unroll
    for (int i = 0; i < 6; i++) {
        o2[i] = addf2(o2[i], __shfl_xor_sync(0xffffffffu, o2[i], 1));
        o2[i] = addf2(o2[i], __shfl_xor_sync(0xffffffffu, o2[i], 2));
    }
    if (part == 0) {
        float o[NP];
#pragma unroll
        for (int i = 0; i < 6; i++) { float2 f = unpk2(o2[i]); o[2*i] = f.x; o[2*i+1] = f.y; }
        float gs = 0.f, gd = 0.f;
#pragma unroll
        for (int p = 0; p < NP; p++) { gs += o[p]*__ldg(ao_src + p); gd += o[p]*__ldg(ao_dst + p); }
        float* op = g_Wh2 + (size_t)bn*NP;
#pragma unroll
        for (int p = 0; p < NP; p++) op[p] = o[p];
        g_gsrc[bn] = gs;
        g_gdst[bn] = gd;
    }
}

// ---------------- K4: layer-2 fused masked softmax + attn2@Wh2 + ELU (f32x2) ----------------
__global__ void __launch_bounds__(512, 1) k_attn2(float* __restrict__ out) {
    extern __shared__ float sm[];
    float* Vs   = sm;
    float* gd_s = sm + NN*NP;
    int b = blockIdx.x >> 3, chunk = blockIdx.x & 7, tid = threadIdx.x;
    const float* Vg = g_Wh2 + (size_t)b*NN*NP;
    for (int i = tid; i < NN*NP; i += 512) Vs[i] = Vg[i];
    for (int i = tid; i < NN; i += 512) gd_s[i] = g_gdst[b*NN + i] * LOG2E;
    __syncthreads();
    int warp = tid >> 5, lane = tid & 31;
#pragma unroll 1
    for (int g = 0; g < 2; g++) {
        int ibase = chunk*128 + warp*8 + g*4;
        float fs[4];
        const uint4* mp[4];
#pragma unroll
        for (int t = 0; t < 4; t++) {
            fs[t] = g_gsrc[b*NN + ibase + t] * LOG2E;
            mp[t] = (const uint4*)(g_mask + (size_t)(ibase + t)*32);
        }
        float z[4] = {0.f, 0.f, 0.f, 0.f};
        unsigned long long acc2[4][6];
#pragma unroll
        for (int t = 0; t < 4; t++)
#pragma unroll
            for (int i = 0; i < 6; i++) acc2[t][i] = 0ull;

#pragma unroll 1
        for (int it4 = 0; it4 < 8; it4++) {
            uint4 mm[4];
#pragma unroll
            for (int t = 0; t < 4; t++) mm[t] = __ldg(mp[t] + it4);
#pragma unroll
            for (int s = 0; s < 4; s++) {
                int j = (it4*4 + s)*32 + lane;
                float gd = gd_s[j];
                const ulonglong2* Vp = (const ulonglong2*)&Vs[j*NP];
                ulonglong2 va = Vp[0], vb = Vp[1], vc = Vp[2];
#pragma unroll
                for (int t = 0; t < 4; t++) {
                    unsigned mwv = (s == 0) ? mm[t].x : (s == 1) ? mm[t].y : (s == 2) ? mm[t].z : mm[t].w;
                    float e = fs[t] + gd; e = fmaxf(e, 0.2f*e);
                    float p = ((mwv >> lane) & 1u) ? ex2f(e) : 0.f;
                    z[t] += p;
                    unsigned long long pp = pack2(p);
                    acc2[t][0] = ffma2(pp, va.x, acc2[t][0]);
                    acc2[t][1] = ffma2(pp, va.y, acc2[t][1]);
                    acc2[t][2] = ffma2(pp, vb.x, acc2[t][2]);
                    acc2[t][3] = ffma2(pp, vb.y, acc2[t][3]);
                    acc2[t][4] = ffma2(pp, vc.x, acc2[t][4]);
                    acc2[t][5] = ffma2(pp, vc.y, acc2[t][5]);
                }
            }
        }
#pragma unroll
        for (int t = 0; t < 4; t++) {
#pragma unroll
            for (int s = 16; s > 0; s >>= 1) {
                z[t] += __shfl_xor_sync(0xffffffffu, z[t], s);
#pragma unroll
                for (int i = 0; i < 6; i++)
                    acc2[t][i] = addf2(acc2[t][i], __shfl_xor_sync(0xffffffffu, acc2[t][i], s));
            }
            if (lane == 0) {
                float invz = 1.f / z[t];
                float* op = out + (size_t)b*NN*NP + (size_t)(ibase + t)*NP;
#pragma unroll
                for (int i = 0; i < 6; i++) {
                    float2 f = unpk2(acc2[t][i]);
                    op[2*i]   = eluf(f.x*invz);
                    op[2*i+1] = eluf(f.y*invz);
                }
            }
        }
    }
}

// ---------------- launch ----------------
extern "C" void kernel_launch(void* const* d_in, const int* in_sizes, int n_in,
                              void* d_out, int out_size) {
    const float* x         = (const float*)d_in[0];
    const int*   adj       = (const int*)  d_in[1];
    const float* W         = (const float*)d_in[2];
    const float* a_src     = (const float*)d_in[3];
    const float* a_dst     = (const float*)d_in[4];
    const float* W_out     = (const float*)d_in[5];
    const float* a_out_src = (const float*)d_in[6];
    const float* a_out_dst = (const float*)d_in[7];
    float* out = (float*)d_out;

    int smem1 = (32*512*2 + NN + 512) * (int)sizeof(float);  // 137216 B
    int smem4 = (NN*NP + NN) * (int)sizeof(float);           // 53248 B
    cudaFuncSetAttribute(k_attn1_b, cudaFuncAttributeMaxDynamicSharedMemorySize, smem1);
    cudaFuncSetAttribute(k_attn2,   cudaFuncAttributeMaxDynamicSharedMemorySize, smem4);

    k_maskA<<<NN/2, NN>>>(adj);
    k_maskB<<<NN/2, NN>>>(adj);
    k_wh<<<dim3(B*HEADS, NN/256), 256>>>(x, W, a_src, a_dst);
    k_attn1_b<<<B*HEADS*2, 512, smem1>>>();
    k_wh2<<<B*NN*4/256, 256>>>(W_out, a_out_src, a_out_dst);
    k_attn2<<<B*8, 512, smem4>>>(out);
}

// round 7
// speedup vs baseline: 3.3728x; 1.2349x over previous
#include <cuda_runtime.h>
#include <cuda_fp16.h>
#include <cstdint>

#define B 16
#define NN 1024
#define NF 16
#define NHID 32
#define HEADS 4
#define NP 12
#define LOG2E 1.4426950408889634f
#define ONES16 0x3C003C00u

__device__ float    g_Wh[B*HEADS*NN*NHID];
__device__ float    g_fsrc[B*HEADS*NN];
__device__ float    g_fdst[B*HEADS*NN];
__device__ unsigned g_mask[NN*NN/32];
__device__ float    g_h[B*NN*HEADS*NHID];
__device__ float    g_Wh2[B*NN*NP];
__device__ float    g_gsrc[B*NN];
__device__ float    g_gdst[B*NN];

__device__ __forceinline__ float ex2f(float x) {
    float y; asm("ex2.approx.f32 %0, %1;" : "=f"(y) : "f"(x)); return y;
}
__device__ __forceinline__ float eluf(float v) { return v > 0.f ? v : (ex2f(v*LOG2E) - 1.f); }

__device__ __forceinline__ unsigned long long ffma2(unsigned long long a, unsigned long long b,
                                                    unsigned long long c) {
    unsigned long long d;
    asm("fma.rn.f32x2 %0, %1, %2, %3;" : "=l"(d) : "l"(a), "l"(b), "l"(c));
    return d;
}
__device__ __forceinline__ unsigned long long addf2(unsigned long long a, unsigned long long b) {
    unsigned long long d;
    asm("add.rn.f32x2 %0, %1, %2;" : "=l"(d) : "l"(a), "l"(b));
    return d;
}
__device__ __forceinline__ unsigned long long mulf2(unsigned long long a, unsigned long long b) {
    unsigned long long d;
    asm("mul.rn.f32x2 %0, %1, %2;" : "=l"(d) : "l"(a), "l"(b));
    return d;
}
__device__ __forceinline__ unsigned long long pack2(float x) {
    unsigned long long d;
    asm("mov.b64 %0, {%1, %2};" : "=l"(d) : "f"(x), "f"(x));
    return d;
}
__device__ __forceinline__ float2 unpk2(unsigned long long v) {
    float2 f;
    asm("mov.b64 {%0, %1}, %2;" : "=f"(f.x), "=f"(f.y) : "l"(v));
    return f;
}
// pack (a->low, b->high) to f16x2
__device__ __forceinline__ uint32_t pk16(float a, float b) {
    uint32_t h;
    asm("cvt.rn.f16x2.f32 %0, %1, %2;" : "=r"(h) : "f"(b), "f"(a));
    return h;
}
__device__ __forceinline__ void mma16h(float* d, const uint32_t* a, uint32_t b0, uint32_t b1) {
    asm("mma.sync.aligned.m16n8k16.row.col.f32.f16.f16.f32 "
        "{%0,%1,%2,%3},{%4,%5,%6,%7},{%8,%9},{%0,%1,%2,%3};"
        : "+f"(d[0]), "+f"(d[1]), "+f"(d[2]), "+f"(d[3])
        : "r"(a[0]), "r"(a[1]), "r"(a[2]), "r"(a[3]), "r"(b0), "r"(b1));
}

// ---------------- K0a/K0b: adjacency -> bitmask (split keeps k_attn1 at launch #4) ----------------
__global__ void k_maskA(const int* __restrict__ adj) {
    int i = blockIdx.x, j = threadIdx.x;
    unsigned bal = __ballot_sync(0xffffffffu, adj[i*NN + j] > 0);
    if ((j & 31) == 0) g_mask[i*32 + (j >> 5)] = bal;
}
__global__ void k_maskB(const int* __restrict__ adj) {
    int i = blockIdx.x + NN/2, j = threadIdx.x;
    unsigned bal = __ballot_sync(0xffffffffu, adj[i*NN + j] > 0);
    if ((j & 31) == 0) g_mask[i*32 + (j >> 5)] = bal;
}

// ---------------- K1: Wh = x@W, f_src/f_dst ----------------
__global__ void k_wh(const float* __restrict__ x, const float* __restrict__ W,
                     const float* __restrict__ a_src, const float* __restrict__ a_dst) {
    __shared__ float Ws[NF*NHID], as_s[NHID], ad_s[NHID];
    int bh = blockIdx.x, b = bh >> 2, h = bh & 3, tid = threadIdx.x;
    for (int i = tid; i < NF*NHID; i += 256) Ws[i] = W[h*NF*NHID + i];
    if (tid < NHID) { as_s[tid] = a_src[h*NHID + tid]; ad_s[tid] = a_dst[h*NHID + tid]; }
    __syncthreads();
    int n = blockIdx.y*256 + tid;
    const float4* xp = (const float4*)(x + ((size_t)b*NN + n)*NF);
    float xf[NF];
#pragma unroll
    for (int i = 0; i < NF/4; i++) {
        float4 v = __ldg(xp + i);
        xf[4*i] = v.x; xf[4*i+1] = v.y; xf[4*i+2] = v.z; xf[4*i+3] = v.w;
    }
    float wh[NHID];
#pragma unroll
    for (int k = 0; k < NHID; k++) wh[k] = 0.f;
#pragma unroll
    for (int f = 0; f < NF; f++) {
        float xv = xf[f];
#pragma unroll
        for (int k = 0; k < NHID; k++) wh[k] += xv * Ws[f*NHID + k];
    }
    float fs = 0.f, fd = 0.f;
#pragma unroll
    for (int k = 0; k < NHID; k++) { fs += wh[k]*as_s[k]; fd += wh[k]*ad_s[k]; }
    float* op = g_Wh + ((size_t)bh*NN + n)*NHID;
#pragma unroll
    for (int k = 0; k < NHID; k += 4)
        *(float4*)(op + k) = make_float4(wh[k], wh[k+1], wh[k+2], wh[k+3]);
    g_fsrc[bh*NN + n] = fs;
    g_fdst[bh*NN + n] = fd;
}

// ---------------- K2: f16 m16n8k16, P single-precision + W hi/lo, Z via ones-MMA ----------------
__global__ void __launch_bounds__(512, 1) k_attn1_h() {
    extern __shared__ float sm[];
    uint32_t* WhHi = (uint32_t*)sm;              // [32][512] f16x2 pairs
    uint32_t* WhLo = WhHi + 32*512;
    float* fd_s = (float*)(WhLo + 32*512);       // 1024

    int tid = threadIdx.x, warp = tid >> 5, lane = tid & 31;
    int r = lane & 3, q = lane >> 2;
    int bh = blockIdx.x >> 1, half = blockIdx.x & 1;
    int b = bh >> 2, h = bh & 3, row0 = half*512;

    // stage W as f16 hi/lo pairs (j even/odd packed)
    const float* Whg = g_Wh + (size_t)bh*NN*NHID;
    for (int idx = tid; idx < NN*NHID/2; idx += 512) {
        int jp = idx >> 5, k = idx & 31;
        float w0 = Whg[(2*jp)*NHID + k];
        float w1 = Whg[(2*jp+1)*NHID + k];
        __half2 hhv = __floats2half2_rn(w0, w1);
        float2 bk = __half22float2(hhv);
        __half2 llv = __floats2half2_rn(w0 - bk.x, w1 - bk.y);
        int jsw = jp ^ ((k & 7) << 2);
        WhHi[k*512 + jsw] = *(uint32_t*)&hhv;
        WhLo[k*512 + jsw] = *(uint32_t*)&llv;
    }
    for (int i = tid; i < NN; i += 512) fd_s[i] = g_fdst[bh*NN + i] * LOG2E;
    __syncthreads();

    const uint4* mp4[4];
    unsigned long long fs2[4];
#pragma unroll
    for (int t = 0; t < 4; t++) {
        int row = row0 + warp*32 + q + 8*t;
        mp4[t] = (const uint4*)(g_mask + (size_t)row*32);
        fs2[t] = pack2(g_fsrc[bh*NN + row] * LOG2E);
    }
    const unsigned long long C02 = pack2(0.2f);

    float acc[2][4][4];
    float accz[2][4];
#pragma unroll
    for (int f = 0; f < 2; f++) {
#pragma unroll
        for (int nt = 0; nt < 4; nt++)
#pragma unroll
            for (int i = 0; i < 4; i++) acc[f][nt][i] = 0.f;
#pragma unroll
        for (int i = 0; i < 4; i++) accz[f][i] = 0.f;
    }

#pragma unroll 1
    for (int gg = 0; gg < 8; gg++) {
        uint4 m4[4];
#pragma unroll
        for (int t = 0; t < 4; t++) m4[t] = __ldg(mp4[t] + gg);
#pragma unroll
        for (int sub = 0; sub < 4; sub++) {
            unsigned mw[4];
#pragma unroll
            for (int t = 0; t < 4; t++)
                mw[t] = (sub == 0) ? m4[t].x : (sub == 1) ? m4[t].y : (sub == 2) ? m4[t].z : m4[t].w;
            int g = gg*4 + sub;
#pragma unroll
            for (int ck = 0; ck < 2; ck++) {
                int j0 = g*32 + ck*16;
                unsigned long long fdA = *(const unsigned long long*)&fd_s[j0 + 2*r];
                unsigned long long fdB = *(const unsigned long long*)&fd_s[j0 + 8 + 2*r];
                uint32_t Ah[2][4];
#pragma unroll
                for (int f = 0; f < 2; f++) {
#pragma unroll
                    for (int hh = 0; hh < 2; hh++) {
                        int t = 2*f + hh;
                        unsigned m = mw[t] >> (ck*16 + 2*r);
                        unsigned long long eA = addf2(fs2[t], fdA);
                        unsigned long long eB = addf2(fs2[t], fdB);
                        unsigned long long lA = mulf2(eA, C02);
                        unsigned long long lB = mulf2(eB, C02);
                        float2 ea = unpk2(eA), la = unpk2(lA);
                        float2 eb = unpk2(eB), lb = unpk2(lB);
                        float x0 = ex2f(fmaxf(ea.x, la.x));
                        float x1 = ex2f(fmaxf(ea.y, la.y));
                        float x8 = ex2f(fmaxf(eb.x, lb.x));
                        float x9 = ex2f(fmaxf(eb.y, lb.y));
                        float p0 = (m & 1u)        ? x0 : 0.f;
                        float p1 = (m & 2u)        ? x1 : 0.f;
                        float p8 = ((m >> 8) & 1u) ? x8 : 0.f;
                        float p9 = ((m >> 9) & 1u) ? x9 : 0.f;
                        Ah[f][hh]     = pk16(p0, p1);
                        Ah[f][2 + hh] = pk16(p8, p9);
                    }
                }
                int jp0 = g*16 + ck*8;
                int sw0 = (jp0 + r)     ^ (q << 2);
                int sw1 = (jp0 + 4 + r) ^ (q << 2);
#pragma unroll
                for (int nt = 0; nt < 4; nt++) {
                    int base = (nt*8 + q) * 512;
                    uint32_t bh0 = WhHi[base + sw0], bh1 = WhHi[base + sw1];
                    uint32_t bl0 = WhLo[base + sw0], bl1 = WhLo[base + sw1];
#pragma unroll
                    for (int f = 0; f < 2; f++) {
                        mma16h(acc[f][nt], Ah[f], bh0, bh1);
                        mma16h(acc[f][nt], Ah[f], bl0, bl1);
                    }
                }
#pragma unroll
                for (int f = 0; f < 2; f++)
                    mma16h(accz[f], Ah[f], ONES16, ONES16);
            }
        }
    }

    // epilogue: per-lane z is in accz (d0 = row q -> node q+16f, d2 = row q+8 -> node q+16f+8)
#pragma unroll
    for (int f = 0; f < 2; f++) {
        float invA = 1.f / accz[f][0];
        float invB = 1.f / accz[f][2];
        int node_lo = row0 + warp*32 + q + 16*f;
        float* base_lo = g_h + ((size_t)(b*NN + node_lo))*(HEADS*NHID) + h*NHID + 2*r;
        float* base_hi = base_lo + 8*(HEADS*NHID);
#pragma unroll
        for (int nt = 0; nt < 4; nt++) {
            float2 v0, v1;
            v0.x = eluf(acc[f][nt][0]*invA);
            v0.y = eluf(acc[f][nt][1]*invA);
            v1.x = eluf(acc[f][nt][2]*invB);
            v1.y = eluf(acc[f][nt][3]*invB);
            *(float2*)(base_lo + nt*8) = v0;
            *(float2*)(base_hi + nt*8) = v1;
        }
    }
}

// ---------------- K3: Wh2 = h@W_out (4-way split, f32x2, rotated conflict-free W) ----------------
__global__ void k_wh2(const float* __restrict__ W_out,
                      const float* __restrict__ ao_src, const float* __restrict__ ao_dst) {
    __shared__ float Wo[128*NP];
    int tid = threadIdx.x;
    for (int i = tid; i < 128*NP; i += 256) Wo[i] = W_out[i];
    __syncthreads();
    int gidx = blockIdx.x*256 + tid;
    int bn = gidx >> 2, part = gidx & 3;
    const float4* hp4 = (const float4*)(g_h + (size_t)bn*128 + part*32);
    unsigned long long o2[6];
#pragma unroll
    for (int i = 0; i < 6; i++) o2[i] = 0ull;
#pragma unroll
    for (int dq = 0; dq < 8; dq++) {
        float4 hv = __ldg(hp4 + dq);
        float hh[4] = {hv.x, hv.y, hv.z, hv.w};
#pragma unroll
        for (int qq = 0; qq < 4; qq++) {
            int qr = (qq + part) & 3;
            int row = part*32 + dq*4 + qr;
            unsigned long long hx2 = pack2(hh[qr]);
            const unsigned long long* wr = (const unsigned long long*)(Wo + row*NP);
#pragma unroll
            for (int i = 0; i < 6; i++) o2[i] = ffma2(hx2, wr[i], o2[i]);
        }
    }
#pragma unroll
    for (int i = 0; i < 6; i++) {
        o2[i] = addf2(o2[i], __shfl_xor_sync(0xffffffffu, o2[i], 1));
        o2[i] = addf2(o2[i], __shfl_xor_sync(0xffffffffu, o2[i], 2));
    }
    if (part == 0) {
        float o[NP];
#pragma unroll
        for (int i = 0; i < 6; i++) { float2 f = unpk2(o2[i]); o[2*i] = f.x; o[2*i+1] = f.y; }
        float gs = 0.f, gd = 0.f;
#pragma unroll
        for (int p = 0; p < NP; p++) { gs += o[p]*__ldg(ao_src + p); gd += o[p]*__ldg(ao_dst + p); }
        float* op = g_Wh2 + (size_t)bn*NP;
#pragma unroll
        for (int p = 0; p < NP; p++) op[p] = o[p];
        g_gsrc[bn] = gs;
        g_gdst[bn] = gd;
    }
}

// ---------------- K4: layer-2 fused masked softmax + attn2@Wh2 + ELU (f32x2) ----------------
__global__ void __launch_bounds__(512, 1) k_attn2(float* __restrict__ out) {
    extern __shared__ float sm[];
    float* Vs   = sm;
    float* gd_s = sm + NN*NP;
    int b = blockIdx.x >> 3, chunk = blockIdx.x & 7, tid = threadIdx.x;
    const float* Vg = g_Wh2 + (size_t)b*NN*NP;
    for (int i = tid; i < NN*NP; i += 512) Vs[i] = Vg[i];
    for (int i = tid; i < NN; i += 512) gd_s[i] = g_gdst[b*NN + i] * LOG2E;
    __syncthreads();
    int warp = tid >> 5, lane = tid & 31;
#pragma unroll 1
    for (int g = 0; g < 2; g++) {
        int ibase = chunk*128 + warp*8 + g*4;
        float fs[4];
        const uint4* mp[4];
#pragma unroll
        for (int t = 0; t < 4; t++) {
            fs[t] = g_gsrc[b*NN + ibase + t] * LOG2E;
            mp[t] = (const uint4*)(g_mask + (size_t)(ibase + t)*32);
        }
        float z[4] = {0.f, 0.f, 0.f, 0.f};
        unsigned long long acc2[4][6];
#pragma unroll
        for (int t = 0; t < 4; t++)
#pragma unroll
            for (int i = 0; i < 6; i++) acc2[t][i] = 0ull;

#pragma unroll 1
        for (int it4 = 0; it4 < 8; it4++) {
            uint4 mm[4];
#pragma unroll
            for (int t = 0; t < 4; t++) mm[t] = __ldg(mp[t] + it4);
#pragma unroll
            for (int s = 0; s < 4; s++) {
                int j = (it4*4 + s)*32 + lane;
                float gd = gd_s[j];
                const ulonglong2* Vp = (const ulonglong2*)&Vs[j*NP];
                ulonglong2 va = Vp[0], vb = Vp[1], vc = Vp[2];
#pragma unroll
                for (int t = 0; t < 4; t++) {
                    unsigned mwv = (s == 0) ? mm[t].x : (s == 1) ? mm[t].y : (s == 2) ? mm[t].z : mm[t].w;
                    float e = fs[t] + gd; e = fmaxf(e, 0.2f*e);
                    float p = ((mwv >> lane) & 1u) ? ex2f(e) : 0.f;
                    z[t] += p;
                    unsigned long long pp = pack2(p);
                    acc2[t][0] = ffma2(pp, va.x, acc2[t][0]);
                    acc2[t][1] = ffma2(pp, va.y, acc2[t][1]);
                    acc2[t][2] = ffma2(pp, vb.x, acc2[t][2]);
                    acc2[t][3] = ffma2(pp, vb.y, acc2[t][3]);
                    acc2[t][4] = ffma2(pp, vc.x, acc2[t][4]);
                    acc2[t][5] = ffma2(pp, vc.y, acc2[t][5]);
                }
            }
        }
#pragma unroll
        for (int t = 0; t < 4; t++) {
#pragma unroll
            for (int s = 16; s > 0; s >>= 1) {
                z[t] += __shfl_xor_sync(0xffffffffu, z[t], s);
#pragma unroll
                for (int i = 0; i < 6; i++)
                    acc2[t][i] = addf2(acc2[t][i], __shfl_xor_sync(0xffffffffu, acc2[t][i], s));
            }
            if (lane == 0) {
                float invz = 1.f / z[t];
                float* op = out + (size_t)b*NN*NP + (size_t)(ibase + t)*NP;
#pragma unroll
                for (int i = 0; i < 6; i++) {
                    float2 f = unpk2(acc2[t][i]);
                    op[2*i]   = eluf(f.x*invz);
                    op[2*i+1] = eluf(f.y*invz);
                }
            }
        }
    }
}

// ---------------- launch ----------------
extern "C" void kernel_launch(void* const* d_in, const int* in_sizes, int n_in,
                              void* d_out, int out_size) {
    const float* x         = (const float*)d_in[0];
    const int*   adj       = (const int*)  d_in[1];
    const float* W         = (const float*)d_in[2];
    const float* a_src     = (const float*)d_in[3];
    const float* a_dst     = (const float*)d_in[4];
    const float* W_out     = (const float*)d_in[5];
    const float* a_out_src = (const float*)d_in[6];
    const float* a_out_dst = (const float*)d_in[7];
    float* out = (float*)d_out;

    int smem1 = (32*512*2 + NN) * (int)sizeof(float);   // 135168 B
    int smem4 = (NN*NP + NN) * (int)sizeof(float);      // 53248 B
    cudaFuncSetAttribute(k_attn1_h, cudaFuncAttributeMaxDynamicSharedMemorySize, smem1);
    cudaFuncSetAttribute(k_attn2,   cudaFuncAttributeMaxDynamicSharedMemorySize, smem4);

    k_maskA<<<NN/2, NN>>>(adj);
    k_maskB<<<NN/2, NN>>>(adj);
    k_wh<<<dim3(B*HEADS, NN/256), 256>>>(x, W, a_src, a_dst);
    k_attn1_h<<<B*HEADS*2, 512, smem1>>>();
    k_wh2<<<B*NN*4/256, 256>>>(W_out, a_out_src, a_out_dst);
    k_attn2<<<B*8, 512, smem4>>>(out);
}

// round 10
// speedup vs baseline: 3.7022x; 1.0977x over previous
#include <cuda_runtime.h>
#include <cuda_fp16.h>
#include <cstdint>

#define B 16
#define NN 1024
#define NF 16
#define NHID 32
#define HEADS 4
#define NP 12
#define LOG2E 1.4426950408889634f
#define ONES16 0x3C003C00u

__device__ float    g_Wh[B*HEADS*NN*NHID];
__device__ float    g_fsrc[B*HEADS*NN];
__device__ float    g_fdst[B*HEADS*NN];
__device__ unsigned g_mask[NN*NN/32];
__device__ float    g_h[B*NN*HEADS*NHID];
__device__ float    g_Wh2[B*NN*NP];
__device__ float    g_gsrc[B*NN];
__device__ float    g_gdst[B*NN];

__device__ __forceinline__ float ex2f(float x) {
    float y; asm("ex2.approx.f32 %0, %1;" : "=f"(y) : "f"(x)); return y;
}
__device__ __forceinline__ float eluf(float v) { return v > 0.f ? v : (ex2f(v*LOG2E) - 1.f); }

__device__ __forceinline__ unsigned long long ffma2(unsigned long long a, unsigned long long b,
                                                    unsigned long long c) {
    unsigned long long d;
    asm("fma.rn.f32x2 %0, %1, %2, %3;" : "=l"(d) : "l"(a), "l"(b), "l"(c));
    return d;
}
__device__ __forceinline__ unsigned long long addf2(unsigned long long a, unsigned long long b) {
    unsigned long long d;
    asm("add.rn.f32x2 %0, %1, %2;" : "=l"(d) : "l"(a), "l"(b));
    return d;
}
__device__ __forceinline__ unsigned long long mulf2(unsigned long long a, unsigned long long b) {
    unsigned long long d;
    asm("mul.rn.f32x2 %0, %1, %2;" : "=l"(d) : "l"(a), "l"(b));
    return d;
}
__device__ __forceinline__ unsigned long long pack2(float x) {
    unsigned long long d;
    asm("mov.b64 %0, {%1, %2};" : "=l"(d) : "f"(x), "f"(x));
    return d;
}
__device__ __forceinline__ float2 unpk2(unsigned long long v) {
    float2 f;
    asm("mov.b64 {%0, %1}, %2;" : "=f"(f.x), "=f"(f.y) : "l"(v));
    return f;
}
// pack (a->low, b->high) to f16x2
__device__ __forceinline__ uint32_t pk16(float a, float b) {
    uint32_t h;
    asm("cvt.rn.f16x2.f32 %0, %1, %2;" : "=r"(h) : "f"(b), "f"(a));
    return h;
}
__device__ __forceinline__ void mma16h(float* d, const uint32_t* a, uint32_t b0, uint32_t b1) {
    asm("mma.sync.aligned.m16n8k16.row.col.f32.f16.f16.f32 "
        "{%0,%1,%2,%3},{%4,%5,%6,%7},{%8,%9},{%0,%1,%2,%3};"
        : "+f"(d[0]), "+f"(d[1]), "+f"(d[2]), "+f"(d[3])
        : "r"(a[0]), "r"(a[1]), "r"(a[2]), "r"(a[3]), "r"(b0), "r"(b1));
}

// ---------------- K0a/K0b: adjacency -> bitmask ----------------
__global__ void k_maskA(const int* __restrict__ adj) {
    int i = blockIdx.x, j = threadIdx.x;
    unsigned bal = __ballot_sync(0xffffffffu, adj[i*NN + j] > 0);
    if ((j & 31) == 0) g_mask[i*32 + (j >> 5)] = bal;
}
__global__ void k_maskB(const int* __restrict__ adj) {
    int i = blockIdx.x + NN/2, j = threadIdx.x;
    unsigned bal = __ballot_sync(0xffffffffu, adj[i*NN + j] > 0);
    if ((j & 31) == 0) g_mask[i*32 + (j >> 5)] = bal;
}

// ---------------- K1: Wh = x@W, f_src/f_dst ----------------
__global__ void k_wh(const float* __restrict__ x, const float* __restrict__ W,
                     const float* __restrict__ a_src, const float* __restrict__ a_dst) {
    __shared__ float Ws[NF*NHID], as_s[NHID], ad_s[NHID];
    int bh = blockIdx.x, b = bh >> 2, h = bh & 3, tid = threadIdx.x;
    for (int i = tid; i < NF*NHID; i += 256) Ws[i] = W[h*NF*NHID + i];
    if (tid < NHID) { as_s[tid] = a_src[h*NHID + tid]; ad_s[tid] = a_dst[h*NHID + tid]; }
    __syncthreads();
    int n = blockIdx.y*256 + tid;
    const float4* xp = (const float4*)(x + ((size_t)b*NN + n)*NF);
    float xf[NF];
#pragma unroll
    for (int i = 0; i < NF/4; i++) {
        float4 v = __ldg(xp + i);
        xf[4*i] = v.x; xf[4*i+1] = v.y; xf[4*i+2] = v.z; xf[4*i+3] = v.w;
    }
    float wh[NHID];
#pragma unroll
    for (int k = 0; k < NHID; k++) wh[k] = 0.f;
#pragma unroll
    for (int f = 0; f < NF; f++) {
        float xv = xf[f];
#pragma unroll
        for (int k = 0; k < NHID; k++) wh[k] += xv * Ws[f*NHID + k];
    }
    float fs = 0.f, fd = 0.f;
#pragma unroll
    for (int k = 0; k < NHID; k++) { fs += wh[k]*as_s[k]; fd += wh[k]*ad_s[k]; }
    float* op = g_Wh + ((size_t)bh*NN + n)*NHID;
#pragma unroll
    for (int k = 0; k < NHID; k += 4)
        *(float4*)(op + k) = make_float4(wh[k], wh[k+1], wh[k+2], wh[k+3]);
    g_fsrc[bh*NN + n] = fs;
    g_fdst[bh*NN + n] = fd;
}

// ---------------- K2: f16 m16n8k16, select masking (R7-proven), W-hi only ----------------
__global__ void __launch_bounds__(512, 1) k_attn1_w() {
    extern __shared__ float sm[];
    uint32_t* WhHi = (uint32_t*)sm;              // [32][512] f16x2 (j even/odd pairs)
    float* fd_s = (float*)(WhHi + 32*512);       // 1024 f32 (fd * LOG2E)

    int tid = threadIdx.x, warp = tid >> 5, lane = tid & 31;
    int r = lane & 3, q = lane >> 2;
    int bh = blockIdx.x >> 1, half = blockIdx.x & 1;
    int b = bh >> 2, h = bh & 3, row0 = half*512;

    const float* Whg = g_Wh + (size_t)bh*NN*NHID;
    for (int idx = tid; idx < NN*NHID/2; idx += 512) {
        int jp = idx >> 5, k = idx & 31;
        float w0 = Whg[(2*jp)*NHID + k];
        float w1 = Whg[(2*jp+1)*NHID + k];
        int jsw = jp ^ ((k & 7) << 2);
        WhHi[k*512 + jsw] = pk16(w0, w1);
    }
    for (int i = tid; i < NN; i += 512) fd_s[i] = g_fdst[bh*NN + i] * LOG2E;
    __syncthreads();

    const uint4* mp4[4];
    unsigned long long fs2[4];
#pragma unroll
    for (int t = 0; t < 4; t++) {
        int row = row0 + warp*32 + q + 8*t;
        mp4[t] = (const uint4*)(g_mask + (size_t)row*32);
        fs2[t] = pack2(g_fsrc[bh*NN + row] * LOG2E);
    }
    const unsigned long long C02 = pack2(0.2f);

    float acc[2][4][4];
    float accz[2][4];
#pragma unroll
    for (int f = 0; f < 2; f++) {
#pragma unroll
        for (int nt = 0; nt < 4; nt++)
#pragma unroll
            for (int i = 0; i < 4; i++) acc[f][nt][i] = 0.f;
#pragma unroll
        for (int i = 0; i < 4; i++) accz[f][i] = 0.f;
    }

#pragma unroll 1
    for (int gg = 0; gg < 8; gg++) {
        uint4 m4[4];
#pragma unroll
        for (int t = 0; t < 4; t++) m4[t] = __ldg(mp4[t] + gg);
#pragma unroll
        for (int sub = 0; sub < 4; sub++) {
            unsigned mw[4];
#pragma unroll
            for (int t = 0; t < 4; t++)
                mw[t] = (sub == 0) ? m4[t].x : (sub == 1) ? m4[t].y : (sub == 2) ? m4[t].z : m4[t].w;
            int g = gg*4 + sub;
#pragma unroll
            for (int ck = 0; ck < 2; ck++) {
                int j0 = g*32 + ck*16;
                unsigned long long fdA = *(const unsigned long long*)&fd_s[j0 + 2*r];
                unsigned long long fdB = *(const unsigned long long*)&fd_s[j0 + 8 + 2*r];
                uint32_t Ah[2][4];
#pragma unroll
                for (int f = 0; f < 2; f++) {
#pragma unroll
                    for (int hh = 0; hh < 2; hh++) {
                        int t = 2*f + hh;
                        unsigned m = mw[t] >> (ck*16 + 2*r);
                        unsigned long long eA = addf2(fs2[t], fdA);
                        unsigned long long eB = addf2(fs2[t], fdB);
                        unsigned long long lA = mulf2(eA, C02);
                        unsigned long long lB = mulf2(eB, C02);
                        float2 ea = unpk2(eA), la = unpk2(lA);
                        float2 eb = unpk2(eB), lb = unpk2(lB);
                        float x0 = ex2f(fmaxf(ea.x, la.x));
                        float x1 = ex2f(fmaxf(ea.y, la.y));
                        float x8 = ex2f(fmaxf(eb.x, lb.x));
                        float x9 = ex2f(fmaxf(eb.y, lb.y));
                        float p0 = (m & 1u)        ? x0 : 0.f;
                        float p1 = (m & 2u)        ? x1 : 0.f;
                        float p8 = ((m >> 8) & 1u) ? x8 : 0.f;
                        float p9 = ((m >> 9) & 1u) ? x9 : 0.f;
                        Ah[f][hh]     = pk16(p0, p1);
                        Ah[f][2 + hh] = pk16(p8, p9);
                    }
                }
                int jpb = g*16 + ck*8;
                int sw0 = (jpb + r)     ^ (q << 2);
                int sw1 = (jpb + 4 + r) ^ (q << 2);
#pragma unroll
                for (int nt = 0; nt < 4; nt++) {
                    int base = (nt*8 + q) * 512;
                    uint32_t bh0 = WhHi[base + sw0], bh1 = WhHi[base + sw1];
#pragma unroll
                    for (int f = 0; f < 2; f++)
                        mma16h(acc[f][nt], Ah[f], bh0, bh1);
                }
#pragma unroll
                for (int f = 0; f < 2; f++)
                    mma16h(accz[f], Ah[f], ONES16, ONES16);
            }
        }
    }

    // epilogue: per-lane z in accz (d0 = row q, d2 = row q+8)
#pragma unroll
    for (int f = 0; f < 2; f++) {
        float invA = 1.f / accz[f][0];
        float invB = 1.f / accz[f][2];
        int node_lo = row0 + warp*32 + q + 16*f;
        float* base_lo = g_h + ((size_t)(b*NN + node_lo))*(HEADS*NHID) + h*NHID + 2*r;
        float* base_hi = base_lo + 8*(HEADS*NHID);
#pragma unroll
        for (int nt = 0; nt < 4; nt++) {
            float2 v0, v1;
            v0.x = eluf(acc[f][nt][0]*invA);
            v0.y = eluf(acc[f][nt][1]*invA);
            v1.x = eluf(acc[f][nt][2]*invB);
            v1.y = eluf(acc[f][nt][3]*invB);
            *(float2*)(base_lo + nt*8) = v0;
            *(float2*)(base_hi + nt*8) = v1;
        }
    }
}

// ---------------- K3: Wh2 = h@W_out (4-way split, f32x2, rotated conflict-free W) ----------------
__global__ void k_wh2(const float* __restrict__ W_out,
                      const float* __restrict__ ao_src, const float* __restrict__ ao_dst) {
    __shared__ float Wo[128*NP];
    int tid = threadIdx.x;
    for (int i = tid; i < 128*NP; i += 256) Wo[i] = W_out[i];
    __syncthreads();
    int gidx = blockIdx.x*256 + tid;
    int bn = gidx >> 2, part = gidx & 3;
    const float4* hp4 = (const float4*)(g_h + (size_t)bn*128 + part*32);
    unsigned long long o2[6];
#pragma unroll
    for (int i = 0; i < 6; i++) o2[i] = 0ull;
#pragma unroll
    for (int dq = 0; dq < 8; dq++) {
        float4 hv = __ldg(hp4 + dq);
        float hh[4] = {hv.x, hv.y, hv.z, hv.w};
#pragma unroll
        for (int qq = 0; qq < 4; qq++) {
            int qr = (qq + part) & 3;
            int row = part*32 + dq*4 + qr;
            unsigned long long hx2 = pack2(hh[qr]);
            const unsigned long long* wr = (const unsigned long long*)(Wo + row*NP);
#pragma unroll
            for (int i = 0; i < 6; i++) o2[i] = ffma2(hx2, wr[i], o2[i]);
        }
    }
#pragma unroll
    for (int i = 0; i < 6; i++) {
        o2[i] = addf2(o2[i], __shfl_xor_sync(0xffffffffu, o2[i], 1));
        o2[i] = addf2(o2[i], __shfl_xor_sync(0xffffffffu, o2[i], 2));
    }
    if (part == 0) {
        float o[NP];
#pragma unroll
        for (int i = 0; i < 6; i++) { float2 f = unpk2(o2[i]); o[2*i] = f.x; o[2*i+1] = f.y; }
        float gs = 0.f, gd = 0.f;
#pragma unroll
        for (int p = 0; p < NP; p++) { gs += o[p]*__ldg(ao_src + p); gd += o[p]*__ldg(ao_dst + p); }
        float* op = g_Wh2 + (size_t)bn*NP;
#pragma unroll
        for (int p = 0; p < NP; p++) op[p] = o[p];
        g_gsrc[bn] = gs;
        g_gdst[bn] = gd;
    }
}

// ---------------- K4: layer-2 fused masked softmax + attn2@Wh2 + ELU (f32x2) ----------------
__global__ void __launch_bounds__(512, 1) k_attn2(float* __restrict__ out) {
    extern __shared__ float sm[];
    float* Vs   = sm;
    float* gd_s = sm + NN*NP;
    int b = blockIdx.x >> 3, chunk = blockIdx.x & 7, tid = threadIdx.x;
    const float* Vg = g_Wh2 + (size_t)b*NN*NP;
    for (int i = tid; i < NN*NP; i += 512) Vs[i] = Vg[i];
    for (int i = tid; i < NN; i += 512) gd_s[i] = g_gdst[b*NN + i] * LOG2E;
    __syncthreads();
    int warp = tid >> 5, lane = tid & 31;
#pragma unroll 1
    for (int g = 0; g < 2; g++) {
        int ibase = chunk*128 + warp*8 + g*4;
        float fs[4];
        const uint4* mp[4];
#pragma unroll
        for (int t = 0; t < 4; t++) {
            fs[t] = g_gsrc[b*NN + ibase + t] * LOG2E;
            mp[t] = (const uint4*)(g_mask + (size_t)(ibase + t)*32);
        }
        float z[4] = {0.f, 0.f, 0.f, 0.f};
        unsigned long long acc2[4][6];
#pragma unroll
        for (int t = 0; t < 4; t++)
#pragma unroll
            for (int i = 0; i < 6; i++) acc2[t][i] = 0ull;

#pragma unroll 1
        for (int it4 = 0; it4 < 8; it4++) {
            uint4 mm[4];
#pragma unroll
            for (int t = 0; t < 4; t++) mm[t] = __ldg(mp[t] + it4);
#pragma unroll
            for (int s = 0; s < 4; s++) {
                int j = (it4*4 + s)*32 + lane;
                float gd = gd_s[j];
                const ulonglong2* Vp = (const ulonglong2*)&Vs[j*NP];
                ulonglong2 va = Vp[0], vb = Vp[1], vc = Vp[2];
#pragma unroll
                for (int t = 0; t < 4; t++) {
                    unsigned mwv = (s == 0) ? mm[t].x : (s == 1) ? mm[t].y : (s == 2) ? mm[t].z : mm[t].w;
                    float e = fs[t] + gd; e = fmaxf(e, 0.2f*e);
                    float p = ((mwv >> lane) & 1u) ? ex2f(e) : 0.f;
                    z[t] += p;
                    unsigned long long pp = pack2(p);
                    acc2[t][0] = ffma2(pp, va.x, acc2[t][0]);
                    acc2[t][1] = ffma2(pp, va.y, acc2[t][1]);
                    acc2[t][2] = ffma2(pp, vb.x, acc2[t][2]);
                    acc2[t][3] = ffma2(pp, vb.y, acc2[t][3]);
                    acc2[t][4] = ffma2(pp, vc.x, acc2[t][4]);
                    acc2[t][5] = ffma2(pp, vc.y, acc2[t][5]);
                }
            }
        }
#pragma unroll
        for (int t = 0; t < 4; t++) {
#pragma unroll
            for (int s = 16; s > 0; s >>= 1) {
                z[t] += __shfl_xor_sync(0xffffffffu, z[t], s);
#pragma unroll
                for (int i = 0; i < 6; i++)
                    acc2[t][i] = addf2(acc2[t][i], __shfl_xor_sync(0xffffffffu, acc2[t][i], s));
            }
            if (lane == 0) {
                float invz = 1.f / z[t];
                float* op = out + (size_t)b*NN*NP + (size_t)(ibase + t)*NP;
#pragma unroll
                for (int i = 0; i < 6; i++) {
                    float2 f = unpk2(acc2[t][i]);
                    op[2*i]   = eluf(f.x*invz);
                    op[2*i+1] = eluf(f.y*invz);
                }
            }
        }
    }
}

// ---------------- launch ----------------
extern "C" void kernel_launch(void* const* d_in, const int* in_sizes, int n_in,
                              void* d_out, int out_size) {
    const float* x         = (const float*)d_in[0];
    const int*   adj       = (const int*)  d_in[1];
    const float* W         = (const float*)d_in[2];
    const float* a_src     = (const float*)d_in[3];
    const float* a_dst     = (const float*)d_in[4];
    const float* W_out     = (const float*)d_in[5];
    const float* a_out_src = (const float*)d_in[6];
    const float* a_out_dst = (const float*)d_in[7];
    float* out = (float*)d_out;

    int smem1 = (32*512 + NN) * (int)sizeof(float);     // 69632 B
    int smem4 = (NN*NP + NN) * (int)sizeof(float);      // 53248 B
    cudaFuncSetAttribute(k_attn1_w, cudaFuncAttributeMaxDynamicSharedMemorySize, smem1);
    cudaFuncSetAttribute(k_attn2,   cudaFuncAttributeMaxDynamicSharedMemorySize, smem4);

    k_maskA<<<NN/2, NN>>>(adj);
    k_maskB<<<NN/2, NN>>>(adj);
    k_wh<<<dim3(B*HEADS, NN/256), 256>>>(x, W, a_src, a_dst);
    k_attn1_w<<<B*HEADS*2, 512, smem1>>>();
    k_wh2<<<B*NN*4/256, 256>>>(W_out, a_out_src, a_out_dst);
    k_attn2<<<B*8, 512, smem4>>>(out);
}

// round 11
// speedup vs baseline: 4.0895x; 1.1046x over previous
#include <cuda_runtime.h>
#include <cuda_fp16.h>
#include <cstdint>

#define B 16
#define NN 1024
#define NF 16
#define NHID 32
#define HEADS 4
#define NP 12
#define LOG2E 1.4426950408889634f
#define ONES16 0x3C003C00u

__device__ float    g_Wh[B*HEADS*NN*NHID];
__device__ float    g_fsrc[B*HEADS*NN];
__device__ float    g_fdst[B*HEADS*NN];
__device__ unsigned g_mask[NN*NN/32];
__device__ float    g_h[B*NN*HEADS*NHID];
__device__ float    g_Wh2[B*NN*NP];
__device__ float    g_gsrc[B*NN];
__device__ float    g_gdst[B*NN];

__device__ __forceinline__ float ex2f(float x) {
    float y; asm("ex2.approx.f32 %0, %1;" : "=f"(y) : "f"(x)); return y;
}
__device__ __forceinline__ float eluf(float v) { return v > 0.f ? v : (ex2f(v*LOG2E) - 1.f); }

__device__ __forceinline__ unsigned long long ffma2(unsigned long long a, unsigned long long b,
                                                    unsigned long long c) {
    unsigned long long d;
    asm("fma.rn.f32x2 %0, %1, %2, %3;" : "=l"(d) : "l"(a), "l"(b), "l"(c));
    return d;
}
__device__ __forceinline__ unsigned long long addf2(unsigned long long a, unsigned long long b) {
    unsigned long long d;
    asm("add.rn.f32x2 %0, %1, %2;" : "=l"(d) : "l"(a), "l"(b));
    return d;
}
__device__ __forceinline__ unsigned long long pack2(float x) {
    unsigned long long d;
    asm("mov.b64 %0, {%1, %2};" : "=l"(d) : "f"(x), "f"(x));
    return d;
}
__device__ __forceinline__ float2 unpk2(unsigned long long v) {
    float2 f;
    asm("mov.b64 {%0, %1}, %2;" : "=f"(f.x), "=f"(f.y) : "l"(v));
    return f;
}
// pack (a->low, b->high) to f16x2
__device__ __forceinline__ uint32_t pk16(float a, float b) {
    uint32_t h;
    asm("cvt.rn.f16x2.f32 %0, %1, %2;" : "=r"(h) : "f"(b), "f"(a));
    return h;
}
// f16x2 packed ops
__device__ __forceinline__ uint32_t hadd2u(uint32_t a, uint32_t b) {
    uint32_t d; asm("add.rn.f16x2 %0, %1, %2;" : "=r"(d) : "r"(a), "r"(b)); return d;
}
__device__ __forceinline__ uint32_t hmul2u(uint32_t a, uint32_t b) {
    uint32_t d; asm("mul.rn.f16x2 %0, %1, %2;" : "=r"(d) : "r"(a), "r"(b)); return d;
}
__device__ __forceinline__ uint32_t hmax2u(uint32_t a, uint32_t b) {
    uint32_t d; asm("max.f16x2 %0, %1, %2;" : "=r"(d) : "r"(a), "r"(b)); return d;
}
__device__ __forceinline__ uint32_t ex2h2(uint32_t a) {
    uint32_t d; asm("ex2.approx.f16x2 %0, %1;" : "=r"(d) : "r"(a)); return d;
}
// raw PTX prmt (generic mode honors the per-nibble msb sign-replicate bit; the
// __byte_perm intrinsic does NOT — that was the R8/R9 bug)
__device__ __forceinline__ uint32_t prmt_sr(uint32_t a, uint32_t b, uint32_t sel) {
    uint32_t d; asm("prmt.b32 %0, %1, %2, %3;" : "=r"(d) : "r"(a), "r"(b), "r"(sel)); return d;
}
__device__ __forceinline__ void mma16h(float* d, const uint32_t* a, uint32_t b0, uint32_t b1) {
    asm("mma.sync.aligned.m16n8k16.row.col.f32.f16.f16.f32 "
        "{%0,%1,%2,%3},{%4,%5,%6,%7},{%8,%9},{%0,%1,%2,%3};"
        : "+f"(d[0]), "+f"(d[1]), "+f"(d[2]), "+f"(d[3])
        : "r"(a[0]), "r"(a[1]), "r"(a[2]), "r"(a[3]), "r"(b0), "r"(b1));
}

// ---------------- K0a/K0b: adjacency -> bitmask ----------------
__global__ void k_maskA(const int* __restrict__ adj) {
    int i = blockIdx.x, j = threadIdx.x;
    unsigned bal = __ballot_sync(0xffffffffu, adj[i*NN + j] > 0);
    if ((j & 31) == 0) g_mask[i*32 + (j >> 5)] = bal;
}
__global__ void k_maskB(const int* __restrict__ adj) {
    int i = blockIdx.x + NN/2, j = threadIdx.x;
    unsigned bal = __ballot_sync(0xffffffffu, adj[i*NN + j] > 0);
    if ((j & 31) == 0) g_mask[i*32 + (j >> 5)] = bal;
}

// ---------------- K1: Wh = x@W (f32x2), f_src/f_dst ----------------
__global__ void k_wh(const float* __restrict__ x, const float* __restrict__ W,
                     const float* __restrict__ a_src, const float* __restrict__ a_dst) {
    __shared__ float Ws[NF*NHID], as_s[NHID], ad_s[NHID];
    int bh = blockIdx.x, b = bh >> 2, h = bh & 3, tid = threadIdx.x;
    for (int i = tid; i < NF*NHID; i += 256) Ws[i] = W[h*NF*NHID + i];
    if (tid < NHID) { as_s[tid] = a_src[h*NHID + tid]; ad_s[tid] = a_dst[h*NHID + tid]; }
    __syncthreads();
    int n = blockIdx.y*256 + tid;
    const float4* xp = (const float4*)(x + ((size_t)b*NN + n)*NF);
    float xf[NF];
#pragma unroll
    for (int i = 0; i < NF/4; i++) {
        float4 v = __ldg(xp + i);
        xf[4*i] = v.x; xf[4*i+1] = v.y; xf[4*i+2] = v.z; xf[4*i+3] = v.w;
    }
    unsigned long long wh2[NHID/2];
#pragma unroll
    for (int k2 = 0; k2 < NHID/2; k2++) wh2[k2] = 0ull;
#pragma unroll
    for (int f = 0; f < NF; f++) {
        unsigned long long xv2 = pack2(xf[f]);
        const unsigned long long* wr = (const unsigned long long*)(Ws + f*NHID);
#pragma unroll
        for (int k2 = 0; k2 < NHID/2; k2++) wh2[k2] = ffma2(xv2, wr[k2], wh2[k2]);
    }
    unsigned long long fs2 = 0ull, fd2 = 0ull;
    const unsigned long long* as2 = (const unsigned long long*)as_s;
    const unsigned long long* ad2 = (const unsigned long long*)ad_s;
#pragma unroll
    for (int k2 = 0; k2 < NHID/2; k2++) {
        fs2 = ffma2(wh2[k2], as2[k2], fs2);
        fd2 = ffma2(wh2[k2], ad2[k2], fd2);
    }
    float2 fsp = unpk2(fs2), fdp = unpk2(fd2);
    unsigned long long* op = (unsigned long long*)(g_Wh + ((size_t)bh*NN + n)*NHID);
#pragma unroll
    for (int k2 = 0; k2 < NHID/2; k2++) op[k2] = wh2[k2];
    g_fsrc[bh*NN + n] = fsp.x + fsp.y;
    g_fdst[bh*NN + n] = fdp.x + fdp.y;
}

// ---------------- K2: f16 m16n8k16, f16x2 score path, PTX-prmt masks, W-hi only ----------------
__global__ void __launch_bounds__(512, 1) k_attn1_f() {
    extern __shared__ float sm[];
    uint32_t* WhHi = (uint32_t*)sm;              // [32][512] f16x2 (j even/odd pairs)
    uint32_t* fd_h = WhHi + 32*512;              // [512] half2 of fd*LOG2E pairs

    int tid = threadIdx.x, warp = tid >> 5, lane = tid & 31;
    int r = lane & 3, q = lane >> 2;
    int bh = blockIdx.x >> 1, half = blockIdx.x & 1;
    int b = bh >> 2, h = bh & 3, row0 = half*512;

    const float* Whg = g_Wh + (size_t)bh*NN*NHID;
    for (int idx = tid; idx < NN*NHID/2; idx += 512) {
        int jp = idx >> 5, k = idx & 31;
        float w0 = Whg[(2*jp)*NHID + k];
        float w1 = Whg[(2*jp+1)*NHID + k];
        int jsw = jp ^ ((k & 7) << 2);
        WhHi[k*512 + jsw] = pk16(w0, w1);
    }
    {
        const float* fdg = g_fdst + bh*NN;
        for (int jp = tid; jp < NN/2; jp += 512)
            fd_h[jp] = pk16(fdg[2*jp]*LOG2E, fdg[2*jp+1]*LOG2E);
    }
    __syncthreads();

    const uint4* mp4[4];
    uint32_t fs2h[4];
#pragma unroll
    for (int t = 0; t < 4; t++) {
        int row = row0 + warp*32 + q + 8*t;
        mp4[t] = (const uint4*)(g_mask + (size_t)row*32);
        float fv = g_fsrc[bh*NN + row] * LOG2E;
        fs2h[t] = pk16(fv, fv);
    }
    const uint32_t C02H = 0x32663266u;  // half2(0.2, 0.2)

    float acc[2][4][4];
    float accz[2][4];
#pragma unroll
    for (int f = 0; f < 2; f++) {
#pragma unroll
        for (int nt = 0; nt < 4; nt++)
#pragma unroll
            for (int i = 0; i < 4; i++) acc[f][nt][i] = 0.f;
#pragma unroll
        for (int i = 0; i < 4; i++) accz[f][i] = 0.f;
    }

#pragma unroll 1
    for (int gg = 0; gg < 8; gg++) {
        uint4 m4[4];
#pragma unroll
        for (int t = 0; t < 4; t++) m4[t] = __ldg(mp4[t] + gg);
#pragma unroll
        for (int sub = 0; sub < 4; sub++) {
            unsigned mw[4];
#pragma unroll
            for (int t = 0; t < 4; t++)
                mw[t] = (sub == 0) ? m4[t].x : (sub == 1) ? m4[t].y : (sub == 2) ? m4[t].z : m4[t].w;
            int g = gg*4 + sub;
#pragma unroll
            for (int ck = 0; ck < 2; ck++) {
                int jp0 = g*16 + ck*8;
                uint32_t fdA = fd_h[jp0 + r];
                uint32_t fdB = fd_h[jp0 + 4 + r];
                uint32_t Ah[2][4];
#pragma unroll
                for (int f = 0; f < 2; f++) {
#pragma unroll
                    for (int hh = 0; hh < 2; hh++) {
                        int t = 2*f + hh;
                        // sign-replicate masks for bits s0=ck*16+2r, s0+1, s0+8, s0+9
                        uint32_t u, v;
                        if (ck == 0) { u = mw[t] << (7 - 2*r);  v = mw[t] << (14 - 2*r); }
                        else         { u = mw[t] >> (2*r + 9);  v = mw[t] >> (2*r + 2);  }
                        uint32_t amaskA = prmt_sr(u, v, 0xDD88u);  // lo16<-bit s0, hi16<-bit s0+1
                        uint32_t amaskB = prmt_sr(u, v, 0xEE99u);  // lo16<-bit s0+8, hi16<-bit s0+9
                        uint32_t eA = hadd2u(fs2h[t], fdA);
                        uint32_t eB = hadd2u(fs2h[t], fdB);
                        eA = hmax2u(eA, hmul2u(eA, C02H));
                        eB = hmax2u(eB, hmul2u(eB, C02H));
                        Ah[f][hh]     = ex2h2(eA) & amaskA;
                        Ah[f][2 + hh] = ex2h2(eB) & amaskB;
                    }
                }
                int sw0 = (jp0 + r)     ^ (q << 2);
                int sw1 = (jp0 + 4 + r) ^ (q << 2);
#pragma unroll
                for (int nt = 0; nt < 4; nt++) {
                    int base = (nt*8 + q) * 512;
                    uint32_t bh0 = WhHi[base + sw0], bh1 = WhHi[base + sw1];
#pragma unroll
                    for (int f = 0; f < 2; f++)
                        mma16h(acc[f][nt], Ah[f], bh0, bh1);
                }
#pragma unroll
                for (int f = 0; f < 2; f++)
                    mma16h(accz[f], Ah[f], ONES16, ONES16);
            }
        }
    }

    // epilogue: per-lane z in accz (d0 = row q, d2 = row q+8)
#pragma unroll
    for (int f = 0; f < 2; f++) {
        float invA = 1.f / accz[f][0];
        float invB = 1.f / accz[f][2];
        int node_lo = row0 + warp*32 + q + 16*f;
        float* base_lo = g_h + ((size_t)(b*NN + node_lo))*(HEADS*NHID) + h*NHID + 2*r;
        float* base_hi = base_lo + 8*(HEADS*NHID);
#pragma unroll
        for (int nt = 0; nt < 4; nt++) {
            float2 v0, v1;
            v0.x = eluf(acc[f][nt][0]*invA);
            v0.y = eluf(acc[f][nt][1]*invA);
            v1.x = eluf(acc[f][nt][2]*invB);
            v1.y = eluf(acc[f][nt][3]*invB);
            *(float2*)(base_lo + nt*8) = v0;
            *(float2*)(base_hi + nt*8) = v1;
        }
    }
}

// ---------------- K3: Wh2 = h@W_out (4-way split, f32x2, rotated conflict-free W) ----------------
__global__ void k_wh2(const float* __restrict__ W_out,
                      const float* __restrict__ ao_src, const float* __restrict__ ao_dst) {
    __shared__ float Wo[128*NP];
    int tid = threadIdx.x;
    for (int i = tid; i < 128*NP; i += 256) Wo[i] = W_out[i];
    __syncthreads();
    int gidx = blockIdx.x*256 + tid;
    int bn = gidx >> 2, part = gidx & 3;
    const float4* hp4 = (const float4*)(g_h + (size_t)bn*128 + part*32);
    unsigned long long o2[6];
#pragma unroll
    for (int i = 0; i < 6; i++) o2[i] = 0ull;
#pragma unroll
    for (int dq = 0; dq < 8; dq++) {
        float4 hv = __ldg(hp4 + dq);
        float hh[4] = {hv.x, hv.y, hv.z, hv.w};
#pragma unroll
        for (int qq = 0; qq < 4; qq++) {
            int qr = (qq + part) & 3;
            int row = part*32 + dq*4 + qr;
            unsigned long long hx2 = pack2(hh[qr]);
            const unsigned long long* wr = (const unsigned long long*)(Wo + row*NP);
#pragma unroll
            for (int i = 0; i < 6; i++) o2[i] = ffma2(hx2, wr[i], o2[i]);
        }
    }
#pragma unroll
    for (int i = 0; i < 6; i++) {
        o2[i] = addf2(o2[i], __shfl_xor_sync(0xffffffffu, o2[i], 1));
        o2[i] = addf2(o2[i], __shfl_xor_sync(0xffffffffu, o2[i], 2));
    }
    if (part == 0) {
        float o[NP];
#pragma unroll
        for (int i = 0; i < 6; i++) { float2 f = unpk2(o2[i]); o[2*i] = f.x; o[2*i+1] = f.y; }
        float gs = 0.f, gd = 0.f;
#pragma unroll
        for (int p = 0; p < NP; p++) { gs += o[p]*__ldg(ao_src + p); gd += o[p]*__ldg(ao_dst + p); }
        float* op = g_Wh2 + (size_t)bn*NP;
#pragma unroll
        for (int p = 0; p < NP; p++) op[p] = o[p];
        g_gsrc[bn] = gs;
        g_gdst[bn] = gd;
    }
}

// ---------------- K4: layer-2 fused masked softmax + attn2@Wh2 + ELU (f32x2) ----------------
__global__ void __launch_bounds__(512, 1) k_attn2(float* __restrict__ out) {
    extern __shared__ float sm[];
    float* Vs   = sm;
    float* gd_s = sm + NN*NP;
    int b = blockIdx.x >> 3, chunk = blockIdx.x & 7, tid = threadIdx.x;
    const float* Vg = g_Wh2 + (size_t)b*NN*NP;
    for (int i = tid; i < NN*NP; i += 512) Vs[i] = Vg[i];
    for (int i = tid; i < NN; i += 512) gd_s[i] = g_gdst[b*NN + i] * LOG2E;
    __syncthreads();
    int warp = tid >> 5, lane = tid & 31;
#pragma unroll 1
    for (int g = 0; g < 2; g++) {
        int ibase = chunk*128 + warp*8 + g*4;
        float fs[4];
        const uint4* mp[4];
#pragma unroll
        for (int t = 0; t < 4; t++) {
            fs[t] = g_gsrc[b*NN + ibase + t] * LOG2E;
            mp[t] = (const uint4*)(g_mask + (size_t)(ibase + t)*32);
        }
        float z[4] = {0.f, 0.f, 0.f, 0.f};
        unsigned long long acc2[4][6];
#pragma unroll
        for (int t = 0; t < 4; t++)
#pragma unroll
            for (int i = 0; i < 6; i++) acc2[t][i] = 0ull;

#pragma unroll 1
        for (int it4 = 0; it4 < 8; it4++) {
            uint4 mm[4];
#pragma unroll
            for (int t = 0; t < 4; t++) mm[t] = __ldg(mp[t] + it4);
#pragma unroll
            for (int s = 0; s < 4; s++) {
                int j = (it4*4 + s)*32 + lane;
                float gd = gd_s[j];
                const ulonglong2* Vp = (const ulonglong2*)&Vs[j*NP];
                ulonglong2 va = Vp[0], vb = Vp[1], vc = Vp[2];
#pragma unroll
                for (int t = 0; t < 4; t++) {
                    unsigned mwv = (s == 0) ? mm[t].x : (s == 1) ? mm[t].y : (s == 2) ? mm[t].z : mm[t].w;
                    float e = fs[t] + gd; e = fmaxf(e, 0.2f*e);
                    float p = ((mwv >> lane) & 1u) ? ex2f(e) : 0.f;
                    z[t] += p;
                    unsigned long long pp = pack2(p);
                    acc2[t][0] = ffma2(pp, va.x, acc2[t][0]);
                    acc2[t][1] = ffma2(pp, va.y, acc2[t][1]);
                    acc2[t][2] = ffma2(pp, vb.x, acc2[t][2]);
                    acc2[t][3] = ffma2(pp, vb.y, acc2[t][3]);
                    acc2[t][4] = ffma2(pp, vc.x, acc2[t][4]);
                    acc2[t][5] = ffma2(pp, vc.y, acc2[t][5]);
                }
            }
        }
#pragma unroll
        for (int t = 0; t < 4; t++) {
#pragma unroll
            for (int s = 16; s > 0; s >>= 1) {
                z[t] += __shfl_xor_sync(0xffffffffu, z[t], s);
#pragma unroll
                for (int i = 0; i < 6; i++)
                    acc2[t][i] = addf2(acc2[t][i], __shfl_xor_sync(0xffffffffu, acc2[t][i], s));
            }
            if (lane == 0) {
                float invz = 1.f / z[t];
                float* op = out + (size_t)b*NN*NP + (size_t)(ibase + t)*NP;
#pragma unroll
                for (int i = 0; i < 6; i++) {
                    float2 f = unpk2(acc2[t][i]);
                    op[2*i]   = eluf(f.x*invz);
                    op[2*i+1] = eluf(f.y*invz);
                }
            }
        }
    }
}

// ---------------- launch ----------------
extern "C" void kernel_launch(void* const* d_in, const int* in_sizes, int n_in,
                              void* d_out, int out_size) {
    const float* x         = (const float*)d_in[0];
    const int*   adj       = (const int*)  d_in[1];
    const float* W         = (const float*)d_in[2];
    const float* a_src     = (const float*)d_in[3];
    const float* a_dst     = (const float*)d_in[4];
    const float* W_out     = (const float*)d_in[5];
    const float* a_out_src = (const float*)d_in[6];
    const float* a_out_dst = (const float*)d_in[7];
    float* out = (float*)d_out;

    int smem1 = (32*512 + 512) * (int)sizeof(float);    // 67584 B
    int smem4 = (NN*NP + NN) * (int)sizeof(float);      // 53248 B
    cudaFuncSetAttribute(k_attn1_f, cudaFuncAttributeMaxDynamicSharedMemorySize, smem1);
    cudaFuncSetAttribute(k_attn2,   cudaFuncAttributeMaxDynamicSharedMemorySize, smem4);

    k_maskA<<<NN/2, NN>>>(adj);
    k_maskB<<<NN/2, NN>>>(adj);
    k_wh<<<dim3(B*HEADS, NN/256), 256>>>(x, W, a_src, a_dst);
    k_attn1_f<<<B*HEADS*2, 512, smem1>>>();
    k_wh2<<<B*NN*4/256, 256>>>(W_out, a_out_src, a_out_dst);
    k_attn2<<<B*8, 512, smem4>>>(out);
}

// round 12
// speedup vs baseline: 4.4220x; 1.0813x over previous
#include <cuda_runtime.h>
#include <cuda_fp16.h>
#include <cstdint>

#define B 16
#define NN 1024
#define NF 16
#define NHID 32
#define HEADS 4
#define NP 12
#define LOG2E 1.4426950408889634f
#define ONES16 0x3C003C00u

__device__ float    g_Wh[B*HEADS*NN*NHID];
__device__ float    g_fsrc[B*HEADS*NN];
__device__ float    g_fdst[B*HEADS*NN];
__device__ unsigned g_mask[NN*NN/32];
__device__ float    g_Wh2[B*NN*NP];

__device__ __forceinline__ float ex2f(float x) {
    float y; asm("ex2.approx.f32 %0, %1;" : "=f"(y) : "f"(x)); return y;
}
__device__ __forceinline__ float eluf(float v) { return v > 0.f ? v : (ex2f(v*LOG2E) - 1.f); }

__device__ __forceinline__ unsigned long long ffma2(unsigned long long a, unsigned long long b,
                                                    unsigned long long c) {
    unsigned long long d;
    asm("fma.rn.f32x2 %0, %1, %2, %3;" : "=l"(d) : "l"(a), "l"(b), "l"(c));
    return d;
}
__device__ __forceinline__ unsigned long long addf2(unsigned long long a, unsigned long long b) {
    unsigned long long d;
    asm("add.rn.f32x2 %0, %1, %2;" : "=l"(d) : "l"(a), "l"(b));
    return d;
}
__device__ __forceinline__ unsigned long long pack2(float x) {
    unsigned long long d;
    asm("mov.b64 %0, {%1, %2};" : "=l"(d) : "f"(x), "f"(x));
    return d;
}
__device__ __forceinline__ float2 unpk2(unsigned long long v) {
    float2 f;
    asm("mov.b64 {%0, %1}, %2;" : "=f"(f.x), "=f"(f.y) : "l"(v));
    return f;
}
__device__ __forceinline__ uint32_t pk16(float a, float b) {
    uint32_t h;
    asm("cvt.rn.f16x2.f32 %0, %1, %2;" : "=r"(h) : "f"(b), "f"(a));
    return h;
}
__device__ __forceinline__ uint32_t hadd2u(uint32_t a, uint32_t b) {
    uint32_t d; asm("add.rn.f16x2 %0, %1, %2;" : "=r"(d) : "r"(a), "r"(b)); return d;
}
__device__ __forceinline__ uint32_t hmul2u(uint32_t a, uint32_t b) {
    uint32_t d; asm("mul.rn.f16x2 %0, %1, %2;" : "=r"(d) : "r"(a), "r"(b)); return d;
}
__device__ __forceinline__ uint32_t hmax2u(uint32_t a, uint32_t b) {
    uint32_t d; asm("max.f16x2 %0, %1, %2;" : "=r"(d) : "r"(a), "r"(b)); return d;
}
__device__ __forceinline__ uint32_t ex2h2(uint32_t a) {
    uint32_t d; asm("ex2.approx.f16x2 %0, %1;" : "=r"(d) : "r"(a)); return d;
}
// raw PTX prmt: generic mode honors per-nibble msb sign-replicate (__byte_perm does NOT)
__device__ __forceinline__ uint32_t prmt_sr(uint32_t a, uint32_t b, uint32_t sel) {
    uint32_t d; asm("prmt.b32 %0, %1, %2, %3;" : "=r"(d) : "r"(a), "r"(b), "r"(sel)); return d;
}
__device__ __forceinline__ void mma16h(float* d, const uint32_t* a, uint32_t b0, uint32_t b1) {
    asm("mma.sync.aligned.m16n8k16.row.col.f32.f16.f16.f32 "
        "{%0,%1,%2,%3},{%4,%5,%6,%7},{%8,%9},{%0,%1,%2,%3};"
        : "+f"(d[0]), "+f"(d[1]), "+f"(d[2]), "+f"(d[3])
        : "r"(a[0]), "r"(a[1]), "r"(a[2]), "r"(a[3]), "r"(b0), "r"(b1));
}

// ---------------- K0a/K0b: adjacency -> bitmask ----------------
__global__ void k_maskA(const int* __restrict__ adj) {
    int i = blockIdx.x, j = threadIdx.x;
    unsigned bal = __ballot_sync(0xffffffffu, adj[i*NN + j] > 0);
    if ((j & 31) == 0) g_mask[i*32 + (j >> 5)] = bal;
}
__global__ void k_maskB(const int* __restrict__ adj) {
    int i = blockIdx.x + NN/2, j = threadIdx.x;
    unsigned bal = __ballot_sync(0xffffffffu, adj[i*NN + j] > 0);
    if ((j & 31) == 0) g_mask[i*32 + (j >> 5)] = bal;
}

// ---------------- K1: Wh = x@W (f32x2), f_src/f_dst; also zero g_Wh2 ----------------
__global__ void k_wh(const float* __restrict__ x, const float* __restrict__ W,
                     const float* __restrict__ a_src, const float* __restrict__ a_dst) {
    __shared__ float Ws[NF*NHID], as_s[NHID], ad_s[NHID];
    int bh = blockIdx.x, b = bh >> 2, h = bh & 3, tid = threadIdx.x;
    // zero g_Wh2 for attn1's atomic accumulation
    int gz = (blockIdx.y*gridDim.x + blockIdx.x)*256 + tid;
    for (int i = gz; i < B*NN*NP; i += 64*4*256) g_Wh2[i] = 0.f;

    for (int i = tid; i < NF*NHID; i += 256) Ws[i] = W[h*NF*NHID + i];
    if (tid < NHID) { as_s[tid] = a_src[h*NHID + tid]; ad_s[tid] = a_dst[h*NHID + tid]; }
    __syncthreads();
    int n = blockIdx.y*256 + tid;
    const float4* xp = (const float4*)(x + ((size_t)b*NN + n)*NF);
    float xf[NF];
#pragma unroll
    for (int i = 0; i < NF/4; i++) {
        float4 v = __ldg(xp + i);
        xf[4*i] = v.x; xf[4*i+1] = v.y; xf[4*i+2] = v.z; xf[4*i+3] = v.w;
    }
    unsigned long long wh2[NHID/2];
#pragma unroll
    for (int k2 = 0; k2 < NHID/2; k2++) wh2[k2] = 0ull;
#pragma unroll
    for (int f = 0; f < NF; f++) {
        unsigned long long xv2 = pack2(xf[f]);
        const unsigned long long* wr = (const unsigned long long*)(Ws + f*NHID);
#pragma unroll
        for (int k2 = 0; k2 < NHID/2; k2++) wh2[k2] = ffma2(xv2, wr[k2], wh2[k2]);
    }
    unsigned long long fs2 = 0ull, fd2 = 0ull;
    const unsigned long long* as2 = (const unsigned long long*)as_s;
    const unsigned long long* ad2 = (const unsigned long long*)ad_s;
#pragma unroll
    for (int k2 = 0; k2 < NHID/2; k2++) {
        fs2 = ffma2(wh2[k2], as2[k2], fs2);
        fd2 = ffma2(wh2[k2], ad2[k2], fd2);
    }
    float2 fsp = unpk2(fs2), fdp = unpk2(fd2);
    unsigned long long* op = (unsigned long long*)(g_Wh + ((size_t)bh*NN + n)*NHID);
#pragma unroll
    for (int k2 = 0; k2 < NHID/2; k2++) op[k2] = wh2[k2];
    g_fsrc[bh*NN + n] = fsp.x + fsp.y;
    g_fdst[bh*NN + n] = fdp.x + fdp.y;
}

// ---------------- K2: fused GAT layer 1 + h@W_out partial (atomic into g_Wh2) ----------------
__global__ void __launch_bounds__(512, 1) k_attn1_f(const float* __restrict__ W_out) {
    extern __shared__ float sm[];
    uint32_t* WhHi = (uint32_t*)sm;              // [32][512] f16x2 (j even/odd pairs)
    uint32_t* fd_h = WhHi + 32*512;              // [512] half2 of fd*LOG2E pairs
    float* Wo = (float*)(fd_h + 512);            // [32][12] W_out slice for this head

    int tid = threadIdx.x, warp = tid >> 5, lane = tid & 31;
    int r = lane & 3, q = lane >> 2;
    int bh = blockIdx.x >> 1, half = blockIdx.x & 1;
    int b = bh >> 2, h = bh & 3, row0 = half*512;

    const float* Whg = g_Wh + (size_t)bh*NN*NHID;
    for (int idx = tid; idx < NN*NHID/2; idx += 512) {
        int jp = idx >> 5, k = idx & 31;
        float w0 = Whg[(2*jp)*NHID + k];
        float w1 = Whg[(2*jp+1)*NHID + k];
        int jsw = jp ^ ((k & 7) << 2);
        WhHi[k*512 + jsw] = pk16(w0, w1);
    }
    {
        const float* fdg = g_fdst + bh*NN;
        for (int jp = tid; jp < NN/2; jp += 512)
            fd_h[jp] = pk16(fdg[2*jp]*LOG2E, fdg[2*jp+1]*LOG2E);
    }
    if (tid < NHID*NP) Wo[tid] = W_out[h*NHID*NP + tid];
    __syncthreads();

    const uint4* mp4[4];
    uint32_t fs2h[4];
#pragma unroll
    for (int t = 0; t < 4; t++) {
        int row = row0 + warp*32 + q + 8*t;
        mp4[t] = (const uint4*)(g_mask + (size_t)row*32);
        float fv = g_fsrc[bh*NN + row] * LOG2E;
        fs2h[t] = pk16(fv, fv);
    }
    const uint32_t C02H = 0x32663266u;  // half2(0.2, 0.2)

    float acc[2][4][4];
    float accz[2][4];
#pragma unroll
    for (int f = 0; f < 2; f++) {
#pragma unroll
        for (int nt = 0; nt < 4; nt++)
#pragma unroll
            for (int i = 0; i < 4; i++) acc[f][nt][i] = 0.f;
#pragma unroll
        for (int i = 0; i < 4; i++) accz[f][i] = 0.f;
    }

#pragma unroll 1
    for (int gg = 0; gg < 8; gg++) {
        uint4 m4[4];
#pragma unroll
        for (int t = 0; t < 4; t++) m4[t] = __ldg(mp4[t] + gg);
#pragma unroll
        for (int sub = 0; sub < 4; sub++) {
            unsigned mw[4];
#pragma unroll
            for (int t = 0; t < 4; t++)
                mw[t] = (sub == 0) ? m4[t].x : (sub == 1) ? m4[t].y : (sub == 2) ? m4[t].z : m4[t].w;
            int g = gg*4 + sub;
            // one shift-pair per row t serves both ck via prmt byte selection:
            // u bytes 0..3 carry sign bits 2r, 2r+8, 2r+16, 2r+24; v likewise +1
            uint32_t us[4], vs[4];
#pragma unroll
            for (int t = 0; t < 4; t++) {
                us[t] = mw[t] << (7 - 2*r);
                vs[t] = mw[t] << (6 - 2*r);
            }
#pragma unroll
            for (int ck = 0; ck < 2; ck++) {
                int jp0 = g*16 + ck*8;
                uint32_t fdA = fd_h[jp0 + r];
                uint32_t fdB = fd_h[jp0 + 4 + r];
                uint32_t selA = ck ? 0xEEAAu : 0xCC88u;
                uint32_t selB = ck ? 0xFFBBu : 0xDD99u;
                uint32_t Ah[2][4];
#pragma unroll
                for (int f = 0; f < 2; f++) {
#pragma unroll
                    for (int hh = 0; hh < 2; hh++) {
                        int t = 2*f + hh;
                        uint32_t amaskA = prmt_sr(us[t], vs[t], selA);
                        uint32_t amaskB = prmt_sr(us[t], vs[t], selB);
                        uint32_t eA = hadd2u(fs2h[t], fdA);
                        uint32_t eB = hadd2u(fs2h[t], fdB);
                        eA = hmax2u(eA, hmul2u(eA, C02H));
                        eB = hmax2u(eB, hmul2u(eB, C02H));
                        Ah[f][hh]     = ex2h2(eA) & amaskA;
                        Ah[f][2 + hh] = ex2h2(eB) & amaskB;
                    }
                }
                int sw0 = (jp0 + r)     ^ (q << 2);
                int sw1 = (jp0 + 4 + r) ^ (q << 2);
#pragma unroll
                for (int nt = 0; nt < 4; nt++) {
                    int base = (nt*8 + q) * 512;
                    uint32_t bh0 = WhHi[base + sw0], bh1 = WhHi[base + sw1];
#pragma unroll
                    for (int f = 0; f < 2; f++)
                        mma16h(acc[f][nt], Ah[f], bh0, bh1);
                }
#pragma unroll
                for (int f = 0; f < 2; f++)
                    mma16h(accz[f], Ah[f], ONES16, ONES16);
            }
        }
    }

    // epilogue: softmax-normalize, ELU, project by W_out slice, quad-reduce, atomic add
#pragma unroll
    for (int f = 0; f < 2; f++) {
#pragma unroll
        for (int rs = 0; rs < 2; rs++) {
            float inv = 1.f / accz[f][2*rs];
            int node = row0 + warp*32 + q + 16*f + 8*rs;
            unsigned long long o2[6];
#pragma unroll
            for (int i = 0; i < 6; i++) o2[i] = 0ull;
#pragma unroll
            for (int nt = 0; nt < 4; nt++) {
                float xx = eluf(acc[f][nt][2*rs]*inv);
                float yy = eluf(acc[f][nt][2*rs+1]*inv);
                unsigned long long x2 = pack2(xx), y2 = pack2(yy);
                const unsigned long long* w0 = (const unsigned long long*)(Wo + (nt*8 + 2*r)*NP);
                const unsigned long long* w1 = (const unsigned long long*)(Wo + (nt*8 + 2*r + 1)*NP);
#pragma unroll
                for (int i = 0; i < 6; i++) {
                    o2[i] = ffma2(x2, w0[i], o2[i]);
                    o2[i] = ffma2(y2, w1[i], o2[i]);
                }
            }
#pragma unroll
            for (int i = 0; i < 6; i++) {
                o2[i] = addf2(o2[i], __shfl_xor_sync(0xffffffffu, o2[i], 1));
                o2[i] = addf2(o2[i], __shfl_xor_sync(0xffffffffu, o2[i], 2));
            }
            if (r == 0) {
                float* dst = g_Wh2 + ((size_t)(b*NN + node))*NP;
#pragma unroll
                for (int i = 0; i < 6; i++) {
                    float2 v = unpk2(o2[i]);
                    atomicAdd(dst + 2*i, v.x);
                    atomicAdd(dst + 2*i + 1, v.y);
                }
            }
        }
    }
}

// ---------------- K3: layer-2 fused (computes g/softmax/AV from g_Wh2 directly) ----------------
__global__ void __launch_bounds__(512, 1) k_attn2(float* __restrict__ out,
                                                  const float* __restrict__ ao_src,
                                                  const float* __restrict__ ao_dst) {
    extern __shared__ float sm[];
    float* Vs   = sm;              // [1024][12]
    float* gd_s = sm + NN*NP;      // [1024]
    float* gs_s = gd_s + NN;       // [1024]
    int b = blockIdx.x >> 3, chunk = blockIdx.x & 7, tid = threadIdx.x;

    float aos[NP], aod[NP];
#pragma unroll
    for (int p = 0; p < NP; p++) { aos[p] = __ldg(ao_src + p); aod[p] = __ldg(ao_dst + p); }

#pragma unroll
    for (int rr = 0; rr < 2; rr++) {
        int j = tid + rr*512;
        const float4* vp = (const float4*)(g_Wh2 + ((size_t)b*NN + j)*NP);
        float4 a0 = __ldg(vp), a1 = __ldg(vp + 1), a2 = __ldg(vp + 2);
        float4* vsp = (float4*)&Vs[j*NP];
        vsp[0] = a0; vsp[1] = a1; vsp[2] = a2;
        float va[NP] = {a0.x, a0.y, a0.z, a0.w, a1.x, a1.y, a1.z, a1.w, a2.x, a2.y, a2.z, a2.w};
        float gs = 0.f, gd = 0.f;
#pragma unroll
        for (int p = 0; p < NP; p++) { gs += va[p]*aos[p]; gd += va[p]*aod[p]; }
        gs_s[j] = gs * LOG2E;
        gd_s[j] = gd * LOG2E;
    }
    __syncthreads();

    int warp = tid >> 5, lane = tid & 31;
#pragma unroll 1
    for (int g = 0; g < 2; g++) {
        int ibase = chunk*128 + warp*8 + g*4;
        float fs[4];
        const uint4* mp[4];
#pragma unroll
        for (int t = 0; t < 4; t++) {
            fs[t] = gs_s[ibase + t];
            mp[t] = (const uint4*)(g_mask + (size_t)(ibase + t)*32);
        }
        float z[4] = {0.f, 0.f, 0.f, 0.f};
        unsigned long long acc2[4][6];
#pragma unroll
        for (int t = 0; t < 4; t++)
#pragma unroll
            for (int i = 0; i < 6; i++) acc2[t][i] = 0ull;

#pragma unroll 1
        for (int it4 = 0; it4 < 8; it4++) {
            uint4 mm[4];
#pragma unroll
            for (int t = 0; t < 4; t++) mm[t] = __ldg(mp[t] + it4);
#pragma unroll
            for (int s = 0; s < 4; s++) {
                int j = (it4*4 + s)*32 + lane;
                float gd = gd_s[j];
                const ulonglong2* Vp = (const ulonglong2*)&Vs[j*NP];
                ulonglong2 va = Vp[0], vb = Vp[1], vc = Vp[2];
#pragma unroll
                for (int t = 0; t < 4; t++) {
                    unsigned mwv = (s == 0) ? mm[t].x : (s == 1) ? mm[t].y : (s == 2) ? mm[t].z : mm[t].w;
                    float e = fs[t] + gd; e = fmaxf(e, 0.2f*e);
                    float p = ((mwv >> lane) & 1u) ? ex2f(e) : 0.f;
                    z[t] += p;
                    unsigned long long pp = pack2(p);
                    acc2[t][0] = ffma2(pp, va.x, acc2[t][0]);
                    acc2[t][1] = ffma2(pp, va.y, acc2[t][1]);
                    acc2[t][2] = ffma2(pp, vb.x, acc2[t][2]);
                    acc2[t][3] = ffma2(pp, vb.y, acc2[t][3]);
                    acc2[t][4] = ffma2(pp, vc.x, acc2[t][4]);
                    acc2[t][5] = ffma2(pp, vc.y, acc2[t][5]);
                }
            }
        }
#pragma unroll
        for (int t = 0; t < 4; t++) {
#pragma unroll
            for (int s = 16; s > 0; s >>= 1) {
                z[t] += __shfl_xor_sync(0xffffffffu, z[t], s);
#pragma unroll
                for (int i = 0; i < 6; i++)
                    acc2[t][i] = addf2(acc2[t][i], __shfl_xor_sync(0xffffffffu, acc2[t][i], s));
            }
            if (lane == 0) {
                float invz = 1.f / z[t];
                float* op = out + (size_t)b*NN*NP + (size_t)(ibase + t)*NP;
#pragma unroll
                for (int i = 0; i < 6; i++) {
                    float2 f = unpk2(acc2[t][i]);
                    op[2*i]   = eluf(f.x*invz);
                    op[2*i+1] = eluf(f.y*invz);
                }
            }
        }
    }
}

// ---------------- launch ----------------
extern "C" void kernel_launch(void* const* d_in, const int* in_sizes, int n_in,
                              void* d_out, int out_size) {
    const float* x         = (const float*)d_in[0];
    const int*   adj       = (const int*)  d_in[1];
    const float* W         = (const float*)d_in[2];
    const float* a_src     = (const float*)d_in[3];
    const float* a_dst     = (const float*)d_in[4];
    const float* W_out     = (const float*)d_in[5];
    const float* a_out_src = (const float*)d_in[6];
    const float* a_out_dst = (const float*)d_in[7];
    float* out = (float*)d_out;

    int smem1 = (32*512 + 512 + NHID*NP) * (int)sizeof(float);   // 69120 B
    int smem4 = (NN*NP + 2*NN) * (int)sizeof(float);             // 57344 B
    cudaFuncSetAttribute(k_attn1_f, cudaFuncAttributeMaxDynamicSharedMemorySize, smem1);
    cudaFuncSetAttribute(k_attn2,   cudaFuncAttributeMaxDynamicSharedMemorySize, smem4);

    k_maskA<<<NN/2, NN>>>(adj);
    k_maskB<<<NN/2, NN>>>(adj);
    k_wh<<<dim3(B*HEADS, NN/256), 256>>>(x, W, a_src, a_dst);
    k_attn1_f<<<B*HEADS*2, 512, smem1>>>(W_out);
    k_attn2<<<B*8, 512, smem4>>>(out, a_out_src, a_out_dst);
}

// round 13
// speedup vs baseline: 4.5673x; 1.0329x over previous
#include <cuda_runtime.h>
#include <cuda_fp16.h>
#include <cstdint>

#define B 16
#define NN 1024
#define NF 16
#define NHID 32
#define HEADS 4
#define NP 12
#define LOG2E 1.4426950408889634f
#define ONES16 0x3C003C00u

__device__ float    g_Wh[B*HEADS*NN*NHID];
__device__ float    g_fsrc[B*HEADS*NN];
__device__ float    g_fdst[B*HEADS*NN];
__device__ unsigned g_mask[NN*NN/32];
__device__ float    g_Wh2p[HEADS*B*NN*NP];   // per-head partial projections

__device__ __forceinline__ float ex2f(float x) {
    float y; asm("ex2.approx.f32 %0, %1;" : "=f"(y) : "f"(x)); return y;
}
__device__ __forceinline__ float eluf(float v) { return v > 0.f ? v : (ex2f(v*LOG2E) - 1.f); }

__device__ __forceinline__ unsigned long long ffma2(unsigned long long a, unsigned long long b,
                                                    unsigned long long c) {
    unsigned long long d;
    asm("fma.rn.f32x2 %0, %1, %2, %3;" : "=l"(d) : "l"(a), "l"(b), "l"(c));
    return d;
}
__device__ __forceinline__ unsigned long long addf2(unsigned long long a, unsigned long long b) {
    unsigned long long d;
    asm("add.rn.f32x2 %0, %1, %2;" : "=l"(d) : "l"(a), "l"(b));
    return d;
}
__device__ __forceinline__ unsigned long long pack2(float x) {
    unsigned long long d;
    asm("mov.b64 %0, {%1, %2};" : "=l"(d) : "f"(x), "f"(x));
    return d;
}
__device__ __forceinline__ float2 unpk2(unsigned long long v) {
    float2 f;
    asm("mov.b64 {%0, %1}, %2;" : "=f"(f.x), "=f"(f.y) : "l"(v));
    return f;
}
__device__ __forceinline__ uint32_t pk16(float a, float b) {
    uint32_t h;
    asm("cvt.rn.f16x2.f32 %0, %1, %2;" : "=r"(h) : "f"(b), "f"(a));
    return h;
}
__device__ __forceinline__ float2 upk16f(uint32_t h) {
    float2 f;
    asm("{ .reg .b16 lo, hi; mov.b32 {lo, hi}, %2; cvt.f32.f16 %0, lo; cvt.f32.f16 %1, hi; }"
        : "=f"(f.x), "=f"(f.y) : "r"(h));
    return f;
}
__device__ __forceinline__ uint32_t hadd2u(uint32_t a, uint32_t b) {
    uint32_t d; asm("add.rn.f16x2 %0, %1, %2;" : "=r"(d) : "r"(a), "r"(b)); return d;
}
__device__ __forceinline__ uint32_t hmul2u(uint32_t a, uint32_t b) {
    uint32_t d; asm("mul.rn.f16x2 %0, %1, %2;" : "=r"(d) : "r"(a), "r"(b)); return d;
}
__device__ __forceinline__ uint32_t hmax2u(uint32_t a, uint32_t b) {
    uint32_t d; asm("max.f16x2 %0, %1, %2;" : "=r"(d) : "r"(a), "r"(b)); return d;
}
__device__ __forceinline__ uint32_t ex2h2(uint32_t a) {
    uint32_t d; asm("ex2.approx.f16x2 %0, %1;" : "=r"(d) : "r"(a)); return d;
}
// raw PTX prmt: generic mode honors per-nibble msb sign-replicate (__byte_perm does NOT)
__device__ __forceinline__ uint32_t prmt_sr(uint32_t a, uint32_t b, uint32_t sel) {
    uint32_t d; asm("prmt.b32 %0, %1, %2, %3;" : "=r"(d) : "r"(a), "r"(b), "r"(sel)); return d;
}
__device__ __forceinline__ void mma16h(float* d, const uint32_t* a, uint32_t b0, uint32_t b1) {
    asm("mma.sync.aligned.m16n8k16.row.col.f32.f16.f16.f32 "
        "{%0,%1,%2,%3},{%4,%5,%6,%7},{%8,%9},{%0,%1,%2,%3};"
        : "+f"(d[0]), "+f"(d[1]), "+f"(d[2]), "+f"(d[3])
        : "r"(a[0]), "r"(a[1]), "r"(a[2]), "r"(a[3]), "r"(b0), "r"(b1));
}

// ---------------- K0a/K0b: adjacency -> bitmask ----------------
__global__ void k_maskA(const int* __restrict__ adj) {
    int i = blockIdx.x, j = threadIdx.x;
    unsigned bal = __ballot_sync(0xffffffffu, adj[i*NN + j] > 0);
    if ((j & 31) == 0) g_mask[i*32 + (j >> 5)] = bal;
}
__global__ void k_maskB(const int* __restrict__ adj) {
    int i = blockIdx.x + NN/2, j = threadIdx.x;
    unsigned bal = __ballot_sync(0xffffffffu, adj[i*NN + j] > 0);
    if ((j & 31) == 0) g_mask[i*32 + (j >> 5)] = bal;
}

// ---------------- K1: Wh = x@W (f32x2), f_src/f_dst ----------------
__global__ void k_wh(const float* __restrict__ x, const float* __restrict__ W,
                     const float* __restrict__ a_src, const float* __restrict__ a_dst) {
    __shared__ float Ws[NF*NHID], as_s[NHID], ad_s[NHID];
    int bh = blockIdx.x, b = bh >> 2, h = bh & 3, tid = threadIdx.x;
    for (int i = tid; i < NF*NHID; i += 256) Ws[i] = W[h*NF*NHID + i];
    if (tid < NHID) { as_s[tid] = a_src[h*NHID + tid]; ad_s[tid] = a_dst[h*NHID + tid]; }
    __syncthreads();
    int n = blockIdx.y*256 + tid;
    const float4* xp = (const float4*)(x + ((size_t)b*NN + n)*NF);
    float xf[NF];
#pragma unroll
    for (int i = 0; i < NF/4; i++) {
        float4 v = __ldg(xp + i);
        xf[4*i] = v.x; xf[4*i+1] = v.y; xf[4*i+2] = v.z; xf[4*i+3] = v.w;
    }
    unsigned long long wh2[NHID/2];
#pragma unroll
    for (int k2 = 0; k2 < NHID/2; k2++) wh2[k2] = 0ull;
#pragma unroll
    for (int f = 0; f < NF; f++) {
        unsigned long long xv2 = pack2(xf[f]);
        const unsigned long long* wr = (const unsigned long long*)(Ws + f*NHID);
#pragma unroll
        for (int k2 = 0; k2 < NHID/2; k2++) wh2[k2] = ffma2(xv2, wr[k2], wh2[k2]);
    }
    unsigned long long fs2 = 0ull, fd2 = 0ull;
    const unsigned long long* as2 = (const unsigned long long*)as_s;
    const unsigned long long* ad2 = (const unsigned long long*)ad_s;
#pragma unroll
    for (int k2 = 0; k2 < NHID/2; k2++) {
        fs2 = ffma2(wh2[k2], as2[k2], fs2);
        fd2 = ffma2(wh2[k2], ad2[k2], fd2);
    }
    float2 fsp = unpk2(fs2), fdp = unpk2(fd2);
    unsigned long long* op = (unsigned long long*)(g_Wh + ((size_t)bh*NN + n)*NHID);
#pragma unroll
    for (int k2 = 0; k2 < NHID/2; k2++) op[k2] = wh2[k2];
    g_fsrc[bh*NN + n] = fsp.x + fsp.y;
    g_fdst[bh*NN + n] = fdp.x + fdp.y;
}

// ---------------- K2: fused GAT layer 1 + h@W_out partial (per-head slice stores) ----------------
__global__ void __launch_bounds__(512, 1) k_attn1_f(const float* __restrict__ W_out) {
    extern __shared__ float sm[];
    uint32_t* WhHi = (uint32_t*)sm;              // [32][512] f16x2 (j even/odd pairs)
    uint32_t* fd_h = WhHi + 32*512;              // [512] half2 of fd*LOG2E pairs
    float* Wo = (float*)(fd_h + 512);            // [32][12] W_out slice for this head

    int tid = threadIdx.x, warp = tid >> 5, lane = tid & 31;
    int r = lane & 3, q = lane >> 2;
    int bh = blockIdx.x >> 1, half = blockIdx.x & 1;
    int b = bh >> 2, h = bh & 3, row0 = half*512;

    const float* Whg = g_Wh + (size_t)bh*NN*NHID;
    for (int idx = tid; idx < NN*NHID/2; idx += 512) {
        int jp = idx >> 5, k = idx & 31;
        float w0 = Whg[(2*jp)*NHID + k];
        float w1 = Whg[(2*jp+1)*NHID + k];
        int jsw = jp ^ ((k & 7) << 2);
        WhHi[k*512 + jsw] = pk16(w0, w1);
    }
    {
        const float* fdg = g_fdst + bh*NN;
        for (int jp = tid; jp < NN/2; jp += 512)
            fd_h[jp] = pk16(fdg[2*jp]*LOG2E, fdg[2*jp+1]*LOG2E);
    }
    if (tid < NHID*NP) Wo[tid] = W_out[h*NHID*NP + tid];
    __syncthreads();

    const uint4* mp4[4];
    uint32_t fs2h[4];
#pragma unroll
    for (int t = 0; t < 4; t++) {
        int row = row0 + warp*32 + q + 8*t;
        mp4[t] = (const uint4*)(g_mask + (size_t)row*32);
        float fv = g_fsrc[bh*NN + row] * LOG2E;
        fs2h[t] = pk16(fv, fv);
    }
    const uint32_t C02H = 0x32663266u;  // half2(0.2, 0.2)

    float acc[2][4][4];
    float accz[2][4];
#pragma unroll
    for (int f = 0; f < 2; f++) {
#pragma unroll
        for (int nt = 0; nt < 4; nt++)
#pragma unroll
            for (int i = 0; i < 4; i++) acc[f][nt][i] = 0.f;
#pragma unroll
        for (int i = 0; i < 4; i++) accz[f][i] = 0.f;
    }

#pragma unroll 1
    for (int gg = 0; gg < 8; gg++) {
        uint4 m4[4];
#pragma unroll
        for (int t = 0; t < 4; t++) m4[t] = __ldg(mp4[t] + gg);
#pragma unroll
        for (int sub = 0; sub < 4; sub++) {
            unsigned mw[4];
#pragma unroll
            for (int t = 0; t < 4; t++)
                mw[t] = (sub == 0) ? m4[t].x : (sub == 1) ? m4[t].y : (sub == 2) ? m4[t].z : m4[t].w;
            int g = gg*4 + sub;
            uint32_t us[4], vs[4];
#pragma unroll
            for (int t = 0; t < 4; t++) {
                us[t] = mw[t] << (7 - 2*r);
                vs[t] = mw[t] << (6 - 2*r);
            }
#pragma unroll
            for (int ck = 0; ck < 2; ck++) {
                int jp0 = g*16 + ck*8;
                uint32_t fdA = fd_h[jp0 + r];
                uint32_t fdB = fd_h[jp0 + 4 + r];
                uint32_t selA = ck ? 0xEEAAu : 0xCC88u;
                uint32_t selB = ck ? 0xFFBBu : 0xDD99u;
                uint32_t Ah[2][4];
#pragma unroll
                for (int f = 0; f < 2; f++) {
#pragma unroll
                    for (int hh = 0; hh < 2; hh++) {
                        int t = 2*f + hh;
                        uint32_t amaskA = prmt_sr(us[t], vs[t], selA);
                        uint32_t amaskB = prmt_sr(us[t], vs[t], selB);
                        uint32_t eA = hadd2u(fs2h[t], fdA);
                        uint32_t eB = hadd2u(fs2h[t], fdB);
                        eA = hmax2u(eA, hmul2u(eA, C02H));
                        eB = hmax2u(eB, hmul2u(eB, C02H));
                        Ah[f][hh]     = ex2h2(eA) & amaskA;
                        Ah[f][2 + hh] = ex2h2(eB) & amaskB;
                    }
                }
                int sw0 = (jp0 + r)     ^ (q << 2);
                int sw1 = (jp0 + 4 + r) ^ (q << 2);
#pragma unroll
                for (int nt = 0; nt < 4; nt++) {
                    int base = (nt*8 + q) * 512;
                    uint32_t bh0 = WhHi[base + sw0], bh1 = WhHi[base + sw1];
#pragma unroll
                    for (int f = 0; f < 2; f++)
                        mma16h(acc[f][nt], Ah[f], bh0, bh1);
                }
#pragma unroll
                for (int f = 0; f < 2; f++)
                    mma16h(accz[f], Ah[f], ONES16, ONES16);
            }
        }
    }

    // epilogue: normalize, ELU, project by W_out slice, quad-reduce, per-head store
#pragma unroll
    for (int f = 0; f < 2; f++) {
#pragma unroll
        for (int rs = 0; rs < 2; rs++) {
            float inv = 1.f / accz[f][2*rs];
            int node = row0 + warp*32 + q + 16*f + 8*rs;
            unsigned long long o2[6];
#pragma unroll
            for (int i = 0; i < 6; i++) o2[i] = 0ull;
#pragma unroll
            for (int nt = 0; nt < 4; nt++) {
                float xx = eluf(acc[f][nt][2*rs]*inv);
                float yy = eluf(acc[f][nt][2*rs+1]*inv);
                unsigned long long x2 = pack2(xx), y2 = pack2(yy);
                const unsigned long long* w0 = (const unsigned long long*)(Wo + (nt*8 + 2*r)*NP);
                const unsigned long long* w1 = (const unsigned long long*)(Wo + (nt*8 + 2*r + 1)*NP);
#pragma unroll
                for (int i = 0; i < 6; i++) {
                    o2[i] = ffma2(x2, w0[i], o2[i]);
                    o2[i] = ffma2(y2, w1[i], o2[i]);
                }
            }
#pragma unroll
            for (int i = 0; i < 6; i++) {
                o2[i] = addf2(o2[i], __shfl_xor_sync(0xffffffffu, o2[i], 1));
                o2[i] = addf2(o2[i], __shfl_xor_sync(0xffffffffu, o2[i], 2));
            }
            if (r == 0) {
                float* dst = g_Wh2p + (((size_t)h*B + b)*NN + node)*NP;
                float2 v0 = unpk2(o2[0]), v1 = unpk2(o2[1]), v2 = unpk2(o2[2]);
                float2 v3 = unpk2(o2[3]), v4 = unpk2(o2[4]), v5 = unpk2(o2[5]);
                *(float4*)dst       = make_float4(v0.x, v0.y, v1.x, v1.y);
                *(float4*)(dst + 4) = make_float4(v2.x, v2.y, v3.x, v3.y);
                *(float4*)(dst + 8) = make_float4(v4.x, v4.y, v5.x, v5.y);
            }
        }
    }
}

// ---------------- K3: layer-2 fused (sums 4 head slices; f16x2-paired exp) ----------------
__global__ void __launch_bounds__(512, 1) k_attn2(float* __restrict__ out,
                                                  const float* __restrict__ ao_src,
                                                  const float* __restrict__ ao_dst) {
    extern __shared__ float sm[];
    float* Vs   = sm;              // [1024][12]
    float* gd_s = sm + NN*NP;      // [1024]
    float* gs_s = gd_s + NN;       // [1024]
    int b = blockIdx.x >> 3, chunk = blockIdx.x & 7, tid = threadIdx.x;

    float aos[NP], aod[NP];
#pragma unroll
    for (int p = 0; p < NP; p++) { aos[p] = __ldg(ao_src + p); aod[p] = __ldg(ao_dst + p); }

#pragma unroll
    for (int rr = 0; rr < 2; rr++) {
        int j = tid + rr*512;
        float4 a0 = make_float4(0.f, 0.f, 0.f, 0.f), a1 = a0, a2 = a0;
#pragma unroll
        for (int hh = 0; hh < HEADS; hh++) {
            const float4* vp = (const float4*)(g_Wh2p + (((size_t)hh*B + b)*NN + j)*NP);
            float4 p0 = __ldg(vp), p1 = __ldg(vp + 1), p2 = __ldg(vp + 2);
            a0.x += p0.x; a0.y += p0.y; a0.z += p0.z; a0.w += p0.w;
            a1.x += p1.x; a1.y += p1.y; a1.z += p1.z; a1.w += p1.w;
            a2.x += p2.x; a2.y += p2.y; a2.z += p2.z; a2.w += p2.w;
        }
        float4* vsp = (float4*)&Vs[j*NP];
        vsp[0] = a0; vsp[1] = a1; vsp[2] = a2;
        float va[NP] = {a0.x, a0.y, a0.z, a0.w, a1.x, a1.y, a1.z, a1.w, a2.x, a2.y, a2.z, a2.w};
        float gs = 0.f, gd = 0.f;
#pragma unroll
        for (int p = 0; p < NP; p++) { gs += va[p]*aos[p]; gd += va[p]*aod[p]; }
        gs_s[j] = gs * LOG2E;
        gd_s[j] = gd * LOG2E;
    }
    __syncthreads();

    int warp = tid >> 5, lane = tid & 31;
#pragma unroll 1
    for (int g = 0; g < 2; g++) {
        int ibase = chunk*128 + warp*8 + g*4;
        float fs[4];
        const uint4* mp[4];
#pragma unroll
        for (int t = 0; t < 4; t++) {
            fs[t] = gs_s[ibase + t];
            mp[t] = (const uint4*)(g_mask + (size_t)(ibase + t)*32);
        }
        float z[4] = {0.f, 0.f, 0.f, 0.f};
        unsigned long long acc2[4][6];
#pragma unroll
        for (int t = 0; t < 4; t++)
#pragma unroll
            for (int i = 0; i < 6; i++) acc2[t][i] = 0ull;

#pragma unroll 1
        for (int it4 = 0; it4 < 8; it4++) {
            uint4 mm[4];
#pragma unroll
            for (int t = 0; t < 4; t++) mm[t] = __ldg(mp[t] + it4);
#pragma unroll
            for (int s = 0; s < 4; s++) {
                int j = (it4*4 + s)*32 + lane;
                float gd = gd_s[j];
                const ulonglong2* Vp = (const ulonglong2*)&Vs[j*NP];
                ulonglong2 va = Vp[0], vb = Vp[1], vc = Vp[2];
#pragma unroll
                for (int tp = 0; tp < 2; tp++) {
                    unsigned m0 = (s == 0) ? mm[2*tp].x : (s == 1) ? mm[2*tp].y : (s == 2) ? mm[2*tp].z : mm[2*tp].w;
                    unsigned m1 = (s == 0) ? mm[2*tp+1].x : (s == 1) ? mm[2*tp+1].y : (s == 2) ? mm[2*tp+1].z : mm[2*tp+1].w;
                    float e0 = fs[2*tp] + gd;   e0 = fmaxf(e0, 0.2f*e0);
                    float e1 = fs[2*tp+1] + gd; e1 = fmaxf(e1, 0.2f*e1);
                    uint32_t p2 = ex2h2(pk16(e0, e1));
                    uint32_t u = m0 << (31 - lane);
                    uint32_t v = m1 << (31 - lane);
                    p2 &= prmt_sr(u, v, 0xFFBBu);
                    float2 pf = upk16f(p2);
                    z[2*tp]   += pf.x;
                    z[2*tp+1] += pf.y;
                    unsigned long long pp0 = pack2(pf.x), pp1 = pack2(pf.y);
                    acc2[2*tp][0]   = ffma2(pp0, va.x, acc2[2*tp][0]);
                    acc2[2*tp][1]   = ffma2(pp0, va.y, acc2[2*tp][1]);
                    acc2[2*tp][2]   = ffma2(pp0, vb.x, acc2[2*tp][2]);
                    acc2[2*tp][3]   = ffma2(pp0, vb.y, acc2[2*tp][3]);
                    acc2[2*tp][4]   = ffma2(pp0, vc.x, acc2[2*tp][4]);
                    acc2[2*tp][5]   = ffma2(pp0, vc.y, acc2[2*tp][5]);
                    acc2[2*tp+1][0] = ffma2(pp1, va.x, acc2[2*tp+1][0]);
                    acc2[2*tp+1][1] = ffma2(pp1, va.y, acc2[2*tp+1][1]);
                    acc2[2*tp+1][2] = ffma2(pp1, vb.x, acc2[2*tp+1][2]);
                    acc2[2*tp+1][3] = ffma2(pp1, vb.y, acc2[2*tp+1][3]);
                    acc2[2*tp+1][4] = ffma2(pp1, vc.x, acc2[2*tp+1][4]);
                    acc2[2*tp+1][5] = ffma2(pp1, vc.y, acc2[2*tp+1][5]);
                }
            }
        }
#pragma unroll
        for (int t = 0; t < 4; t++) {
#pragma unroll
            for (int s = 16; s > 0; s >>= 1) {
                z[t] += __shfl_xor_sync(0xffffffffu, z[t], s);
#pragma unroll
                for (int i = 0; i < 6; i++)
                    acc2[t][i] = addf2(acc2[t][i], __shfl_xor_sync(0xffffffffu, acc2[t][i], s));
            }
            if (lane == 0) {
                float invz = 1.f / z[t];
                float* op = out + (size_t)b*NN*NP + (size_t)(ibase + t)*NP;
#pragma unroll
                for (int i = 0; i < 6; i++) {
                    float2 f = unpk2(acc2[t][i]);
                    op[2*i]   = eluf(f.x*invz);
                    op[2*i+1] = eluf(f.y*invz);
                }
            }
        }
    }
}

// ---------------- launch ----------------
extern "C" void kernel_launch(void* const* d_in, const int* in_sizes, int n_in,
                              void* d_out, int out_size) {
    const float* x         = (const float*)d_in[0];
    const int*   adj       = (const int*)  d_in[1];
    const float* W         = (const float*)d_in[2];
    const float* a_src     = (const float*)d_in[3];
    const float* a_dst     = (const float*)d_in[4];
    const float* W_out     = (const float*)d_in[5];
    const float* a_out_src = (const float*)d_in[6];
    const float* a_out_dst = (const float*)d_in[7];
    float* out = (float*)d_out;

    int smem1 = (32*512 + 512 + NHID*NP) * (int)sizeof(float);   // 69120 B
    int smem4 = (NN*NP + 2*NN) * (int)sizeof(float);             // 57344 B
    cudaFuncSetAttribute(k_attn1_f, cudaFuncAttributeMaxDynamicSharedMemorySize, smem1);
    cudaFuncSetAttribute(k_attn2,   cudaFuncAttributeMaxDynamicSharedMemorySize, smem4);

    k_maskA<<<NN/2, NN>>>(adj);
    k_maskB<<<NN/2, NN>>>(adj);
    k_wh<<<dim3(B*HEADS, NN/256), 256>>>(x, W, a_src, a_dst);
    k_attn1_f<<<B*HEADS*2, 512, smem1>>>(W_out);
    k_attn2<<<B*8, 512, smem4>>>(out, a_out_src, a_out_dst);
}

// round 14
// speedup vs baseline: 5.7118x; 1.2506x over previous
#include <cuda_runtime.h>
#include <cuda_fp16.h>
#include <cstdint>

#define B 16
#define NN 1024
#define NF 16
#define NHID 32
#define HEADS 4
#define NP 12
#define LOG2E 1.4426950408889634f
#define ONES16 0x3C003C00u

__device__ float    g_Wh[B*HEADS*NN*NHID];
__device__ float    g_fsrc[B*HEADS*NN];
__device__ float    g_fdst[B*HEADS*NN];
__device__ unsigned g_mask[NN*NN/32];
__device__ float    g_Wh2p[HEADS*B*NN*NP];   // per-head partial projections

__device__ __forceinline__ float ex2f(float x) {
    float y; asm("ex2.approx.f32 %0, %1;" : "=f"(y) : "f"(x)); return y;
}
__device__ __forceinline__ float eluf(float v) { return v > 0.f ? v : (ex2f(v*LOG2E) - 1.f); }

__device__ __forceinline__ unsigned long long ffma2(unsigned long long a, unsigned long long b,
                                                    unsigned long long c) {
    unsigned long long d;
    asm("fma.rn.f32x2 %0, %1, %2, %3;" : "=l"(d) : "l"(a), "l"(b), "l"(c));
    return d;
}
__device__ __forceinline__ unsigned long long addf2(unsigned long long a, unsigned long long b) {
    unsigned long long d;
    asm("add.rn.f32x2 %0, %1, %2;" : "=l"(d) : "l"(a), "l"(b));
    return d;
}
__device__ __forceinline__ unsigned long long pack2(float x) {
    unsigned long long d;
    asm("mov.b64 %0, {%1, %2};" : "=l"(d) : "f"(x), "f"(x));
    return d;
}
__device__ __forceinline__ float2 unpk2(unsigned long long v) {
    float2 f;
    asm("mov.b64 {%0, %1}, %2;" : "=f"(f.x), "=f"(f.y) : "l"(v));
    return f;
}
__device__ __forceinline__ uint32_t pk16(float a, float b) {
    uint32_t h;
    asm("cvt.rn.f16x2.f32 %0, %1, %2;" : "=r"(h) : "f"(b), "f"(a));
    return h;
}
__device__ __forceinline__ uint32_t hadd2u(uint32_t a, uint32_t b) {
    uint32_t d; asm("add.rn.f16x2 %0, %1, %2;" : "=r"(d) : "r"(a), "r"(b)); return d;
}
__device__ __forceinline__ uint32_t hmul2u(uint32_t a, uint32_t b) {
    uint32_t d; asm("mul.rn.f16x2 %0, %1, %2;" : "=r"(d) : "r"(a), "r"(b)); return d;
}
__device__ __forceinline__ uint32_t hmax2u(uint32_t a, uint32_t b) {
    uint32_t d; asm("max.f16x2 %0, %1, %2;" : "=r"(d) : "r"(a), "r"(b)); return d;
}
__device__ __forceinline__ uint32_t ex2h2(uint32_t a) {
    uint32_t d; asm("ex2.approx.f16x2 %0, %1;" : "=r"(d) : "r"(a)); return d;
}
// raw PTX prmt: generic mode honors per-nibble msb sign-replicate (__byte_perm does NOT)
__device__ __forceinline__ uint32_t prmt_sr(uint32_t a, uint32_t b, uint32_t sel) {
    uint32_t d; asm("prmt.b32 %0, %1, %2, %3;" : "=r"(d) : "r"(a), "r"(b), "r"(sel)); return d;
}
__device__ __forceinline__ void mma16h(float* d, const uint32_t* a, uint32_t b0, uint32_t b1) {
    asm("mma.sync.aligned.m16n8k16.row.col.f32.f16.f16.f32 "
        "{%0,%1,%2,%3},{%4,%5,%6,%7},{%8,%9},{%0,%1,%2,%3};"
        : "+f"(d[0]), "+f"(d[1]), "+f"(d[2]), "+f"(d[3])
        : "r"(a[0]), "r"(a[1]), "r"(a[2]), "r"(a[3]), "r"(b0), "r"(b1));
}

// ---------------- K0: adjacency -> bitmask (fused; keeps attn2 at launch #4) ----------------
__global__ void k_mask(const int* __restrict__ adj) {
    int i = blockIdx.x, j = threadIdx.x;
    unsigned bal = __ballot_sync(0xffffffffu, adj[i*NN + j] > 0);
    if ((j & 31) == 0) g_mask[i*32 + (j >> 5)] = bal;
}

// ---------------- K1: Wh = x@W (f32x2), f_src/f_dst ----------------
__global__ void k_wh(const float* __restrict__ x, const float* __restrict__ W,
                     const float* __restrict__ a_src, const float* __restrict__ a_dst) {
    __shared__ float Ws[NF*NHID], as_s[NHID], ad_s[NHID];
    int bh = blockIdx.x, b = bh >> 2, h = bh & 3, tid = threadIdx.x;
    for (int i = tid; i < NF*NHID; i += 256) Ws[i] = W[h*NF*NHID + i];
    if (tid < NHID) { as_s[tid] = a_src[h*NHID + tid]; ad_s[tid] = a_dst[h*NHID + tid]; }
    __syncthreads();
    int n = blockIdx.y*256 + tid;
    const float4* xp = (const float4*)(x + ((size_t)b*NN + n)*NF);
    float xf[NF];
#pragma unroll
    for (int i = 0; i < NF/4; i++) {
        float4 v = __ldg(xp + i);
        xf[4*i] = v.x; xf[4*i+1] = v.y; xf[4*i+2] = v.z; xf[4*i+3] = v.w;
    }
    unsigned long long wh2[NHID/2];
#pragma unroll
    for (int k2 = 0; k2 < NHID/2; k2++) wh2[k2] = 0ull;
#pragma unroll
    for (int f = 0; f < NF; f++) {
        unsigned long long xv2 = pack2(xf[f]);
        const unsigned long long* wr = (const unsigned long long*)(Ws + f*NHID);
#pragma unroll
        for (int k2 = 0; k2 < NHID/2; k2++) wh2[k2] = ffma2(xv2, wr[k2], wh2[k2]);
    }
    unsigned long long fs2 = 0ull, fd2 = 0ull;
    const unsigned long long* as2 = (const unsigned long long*)as_s;
    const unsigned long long* ad2 = (const unsigned long long*)ad_s;
#pragma unroll
    for (int k2 = 0; k2 < NHID/2; k2++) {
        fs2 = ffma2(wh2[k2], as2[k2], fs2);
        fd2 = ffma2(wh2[k2], ad2[k2], fd2);
    }
    float2 fsp = unpk2(fs2), fdp = unpk2(fd2);
    unsigned long long* op = (unsigned long long*)(g_Wh + ((size_t)bh*NN + n)*NHID);
#pragma unroll
    for (int k2 = 0; k2 < NHID/2; k2++) op[k2] = wh2[k2];
    g_fsrc[bh*NN + n] = fsp.x + fsp.y;
    g_fdst[bh*NN + n] = fdp.x + fdp.y;
}

// ---------------- K2: fused GAT layer 1 + h@W_out partial (per-head slice stores) ----------------
__global__ void __launch_bounds__(512, 1) k_attn1_f(const float* __restrict__ W_out) {
    extern __shared__ float sm[];
    uint32_t* WhHi = (uint32_t*)sm;              // [32][512] f16x2 (j even/odd pairs)
    uint32_t* fd_h = WhHi + 32*512;              // [512] half2 of fd*LOG2E pairs
    float* Wo = (float*)(fd_h + 512);            // [32][12] W_out slice for this head

    int tid = threadIdx.x, warp = tid >> 5, lane = tid & 31;
    int r = lane & 3, q = lane >> 2;
    int bh = blockIdx.x >> 1, half = blockIdx.x & 1;
    int b = bh >> 2, h = bh & 3, row0 = half*512;

    const float* Whg = g_Wh + (size_t)bh*NN*NHID;
    for (int idx = tid; idx < NN*NHID/2; idx += 512) {
        int jp = idx >> 5, k = idx & 31;
        float w0 = Whg[(2*jp)*NHID + k];
        float w1 = Whg[(2*jp+1)*NHID + k];
        int jsw = jp ^ ((k & 7) << 2);
        WhHi[k*512 + jsw] = pk16(w0, w1);
    }
    {
        const float* fdg = g_fdst + bh*NN;
        for (int jp = tid; jp < NN/2; jp += 512)
            fd_h[jp] = pk16(fdg[2*jp]*LOG2E, fdg[2*jp+1]*LOG2E);
    }
    if (tid < NHID*NP) Wo[tid] = W_out[h*NHID*NP + tid];
    __syncthreads();

    const uint4* mp4[4];
    uint32_t fs2h[4];
#pragma unroll
    for (int t = 0; t < 4; t++) {
        int row = row0 + warp*32 + q + 8*t;
        mp4[t] = (const uint4*)(g_mask + (size_t)row*32);
        float fv = g_fsrc[bh*NN + row] * LOG2E;
        fs2h[t] = pk16(fv, fv);
    }
    const uint32_t C02H = 0x32663266u;

    float acc[2][4][4];
    float accz[2][4];
#pragma unroll
    for (int f = 0; f < 2; f++) {
#pragma unroll
        for (int nt = 0; nt < 4; nt++)
#pragma unroll
            for (int i = 0; i < 4; i++) acc[f][nt][i] = 0.f;
#pragma unroll
        for (int i = 0; i < 4; i++) accz[f][i] = 0.f;
    }

#pragma unroll 1
    for (int gg = 0; gg < 8; gg++) {
        uint4 m4[4];
#pragma unroll
        for (int t = 0; t < 4; t++) m4[t] = __ldg(mp4[t] + gg);
#pragma unroll
        for (int sub = 0; sub < 4; sub++) {
            unsigned mw[4];
#pragma unroll
            for (int t = 0; t < 4; t++)
                mw[t] = (sub == 0) ? m4[t].x : (sub == 1) ? m4[t].y : (sub == 2) ? m4[t].z : m4[t].w;
            int g = gg*4 + sub;
            uint32_t us[4], vs[4];
#pragma unroll
            for (int t = 0; t < 4; t++) {
                us[t] = mw[t] << (7 - 2*r);
                vs[t] = mw[t] << (6 - 2*r);
            }
#pragma unroll
            for (int ck = 0; ck < 2; ck++) {
                int jp0 = g*16 + ck*8;
                uint32_t fdA = fd_h[jp0 + r];
                uint32_t fdB = fd_h[jp0 + 4 + r];
                uint32_t selA = ck ? 0xEEAAu : 0xCC88u;
                uint32_t selB = ck ? 0xFFBBu : 0xDD99u;
                uint32_t Ah[2][4];
#pragma unroll
                for (int f = 0; f < 2; f++) {
#pragma unroll
                    for (int hh = 0; hh < 2; hh++) {
                        int t = 2*f + hh;
                        uint32_t amaskA = prmt_sr(us[t], vs[t], selA);
                        uint32_t amaskB = prmt_sr(us[t], vs[t], selB);
                        uint32_t eA = hadd2u(fs2h[t], fdA);
                        uint32_t eB = hadd2u(fs2h[t], fdB);
                        eA = hmax2u(eA, hmul2u(eA, C02H));
                        eB = hmax2u(eB, hmul2u(eB, C02H));
                        Ah[f][hh]     = ex2h2(eA) & amaskA;
                        Ah[f][2 + hh] = ex2h2(eB) & amaskB;
                    }
                }
                int sw0 = (jp0 + r)     ^ (q << 2);
                int sw1 = (jp0 + 4 + r) ^ (q << 2);
#pragma unroll
                for (int nt = 0; nt < 4; nt++) {
                    int base = (nt*8 + q) * 512;
                    uint32_t bh0 = WhHi[base + sw0], bh1 = WhHi[base + sw1];
#pragma unroll
                    for (int f = 0; f < 2; f++)
                        mma16h(acc[f][nt], Ah[f], bh0, bh1);
                }
#pragma unroll
                for (int f = 0; f < 2; f++)
                    mma16h(accz[f], Ah[f], ONES16, ONES16);
            }
        }
    }

#pragma unroll
    for (int f = 0; f < 2; f++) {
#pragma unroll
        for (int rs = 0; rs < 2; rs++) {
            float inv = 1.f / accz[f][2*rs];
            int node = row0 + warp*32 + q + 16*f + 8*rs;
            unsigned long long o2[6];
#pragma unroll
            for (int i = 0; i < 6; i++) o2[i] = 0ull;
#pragma unroll
            for (int nt = 0; nt < 4; nt++) {
                float xx = eluf(acc[f][nt][2*rs]*inv);
                float yy = eluf(acc[f][nt][2*rs+1]*inv);
                unsigned long long x2 = pack2(xx), y2 = pack2(yy);
                const unsigned long long* w0 = (const unsigned long long*)(Wo + (nt*8 + 2*r)*NP);
                const unsigned long long* w1 = (const unsigned long long*)(Wo + (nt*8 + 2*r + 1)*NP);
#pragma unroll
                for (int i = 0; i < 6; i++) {
                    o2[i] = ffma2(x2, w0[i], o2[i]);
                    o2[i] = ffma2(y2, w1[i], o2[i]);
                }
            }
#pragma unroll
            for (int i = 0; i < 6; i++) {
                o2[i] = addf2(o2[i], __shfl_xor_sync(0xffffffffu, o2[i], 1));
                o2[i] = addf2(o2[i], __shfl_xor_sync(0xffffffffu, o2[i], 2));
            }
            if (r == 0) {
                float* dst = g_Wh2p + (((size_t)h*B + b)*NN + node)*NP;
                float2 v0 = unpk2(o2[0]), v1 = unpk2(o2[1]), v2 = unpk2(o2[2]);
                float2 v3 = unpk2(o2[3]), v4 = unpk2(o2[4]), v5 = unpk2(o2[5]);
                *(float4*)dst       = make_float4(v0.x, v0.y, v1.x, v1.y);
                *(float4*)(dst + 4) = make_float4(v2.x, v2.y, v3.x, v3.y);
                *(float4*)(dst + 8) = make_float4(v4.x, v4.y, v5.x, v5.y);
            }
        }
    }
}

// ---------------- K3: layer-2 via mma (V padded to 16 cols), warp = (row-tile, j-quarter) ----------------
__global__ void __launch_bounds__(512, 1) k_attn2_m(float* __restrict__ out,
                                                    const float* __restrict__ ao_src,
                                                    const float* __restrict__ ao_dst) {
    extern __shared__ float sm[];
    uint32_t* Vh   = (uint32_t*)sm;              // [16][512] f16x2 pairs (cols 12-15 zero)
    uint32_t* gd_h = Vh + 16*512;                // [512] half2 of gd*LOG2E
    float* gs_s    = (float*)(gd_h + 512);       // [1024]
    float* red     = gs_s + NN;                  // [3][4][32][21]

    int tid = threadIdx.x, warp = tid >> 5, lane = tid & 31;
    int r = lane & 3, q = lane >> 2;
    int b = blockIdx.x >> 3, chunk = blockIdx.x & 7;
    int row0 = chunk*128;

    // stage: sum 4 head slices for node pair (2*tid, 2*tid+1), pack to f16, compute gs/gd
    {
        int jp = tid;
        float va[24];
#pragma unroll
        for (int i = 0; i < 24; i++) va[i] = 0.f;
#pragma unroll
        for (int hh = 0; hh < HEADS; hh++) {
            const float4* vp = (const float4*)(g_Wh2p + (((size_t)hh*B + b)*NN + 2*jp)*NP);
#pragma unroll
            for (int i = 0; i < 6; i++) {
                float4 p = __ldg(vp + i);
                va[4*i] += p.x; va[4*i+1] += p.y; va[4*i+2] += p.z; va[4*i+3] += p.w;
            }
        }
#pragma unroll
        for (int c = 0; c < NP; c++)
            Vh[c*512 + (jp ^ ((c & 7) << 2))] = pk16(va[c], va[12 + c]);
#pragma unroll
        for (int c = NP; c < 16; c++)
            Vh[c*512 + (jp ^ ((c & 7) << 2))] = 0u;
        float gs0 = 0.f, gd0 = 0.f, gs1 = 0.f, gd1 = 0.f;
#pragma unroll
        for (int p = 0; p < NP; p++) {
            float as = __ldg(ao_src + p), ad = __ldg(ao_dst + p);
            gs0 += va[p]*as;      gd0 += va[p]*ad;
            gs1 += va[12 + p]*as; gd1 += va[12 + p]*ad;
        }
        gs_s[2*jp]     = gs0 * LOG2E;
        gs_s[2*jp + 1] = gs1 * LOG2E;
        gd_h[jp] = pk16(gd0 * LOG2E, gd1 * LOG2E);
    }
    __syncthreads();

    int rw = warp & 3, jseg = warp >> 2;
    const uint4* mp4[4];
    uint32_t fs2h[4];
#pragma unroll
    for (int t = 0; t < 4; t++) {
        int row = row0 + rw*32 + q + 8*t;
        mp4[t] = (const uint4*)(g_mask + (size_t)row*32);
        float fv = gs_s[row];
        fs2h[t] = pk16(fv, fv);
    }
    const uint32_t C02H = 0x32663266u;

    float acc[2][2][4];
    float accz[2][4];
#pragma unroll
    for (int f = 0; f < 2; f++) {
#pragma unroll
        for (int nt = 0; nt < 2; nt++)
#pragma unroll
            for (int i = 0; i < 4; i++) acc[f][nt][i] = 0.f;
#pragma unroll
        for (int i = 0; i < 4; i++) accz[f][i] = 0.f;
    }

#pragma unroll 1
    for (int gi = 0; gi < 2; gi++) {
        int gg = jseg*2 + gi;
        uint4 m4[4];
#pragma unroll
        for (int t = 0; t < 4; t++) m4[t] = __ldg(mp4[t] + gg);
#pragma unroll
        for (int sub = 0; sub < 4; sub++) {
            unsigned mw[4];
#pragma unroll
            for (int t = 0; t < 4; t++)
                mw[t] = (sub == 0) ? m4[t].x : (sub == 1) ? m4[t].y : (sub == 2) ? m4[t].z : m4[t].w;
            int g = gg*4 + sub;
            uint32_t us[4], vs[4];
#pragma unroll
            for (int t = 0; t < 4; t++) {
                us[t] = mw[t] << (7 - 2*r);
                vs[t] = mw[t] << (6 - 2*r);
            }
#pragma unroll
            for (int ck = 0; ck < 2; ck++) {
                int jp0 = g*16 + ck*8;
                uint32_t fdA = gd_h[jp0 + r];
                uint32_t fdB = gd_h[jp0 + 4 + r];
                uint32_t selA = ck ? 0xEEAAu : 0xCC88u;
                uint32_t selB = ck ? 0xFFBBu : 0xDD99u;
                uint32_t Ah[2][4];
#pragma unroll
                for (int f = 0; f < 2; f++) {
#pragma unroll
                    for (int hh = 0; hh < 2; hh++) {
                        int t = 2*f + hh;
                        uint32_t amaskA = prmt_sr(us[t], vs[t], selA);
                        uint32_t amaskB = prmt_sr(us[t], vs[t], selB);
                        uint32_t eA = hadd2u(fs2h[t], fdA);
                        uint32_t eB = hadd2u(fs2h[t], fdB);
                        eA = hmax2u(eA, hmul2u(eA, C02H));
                        eB = hmax2u(eB, hmul2u(eB, C02H));
                        Ah[f][hh]     = ex2h2(eA) & amaskA;
                        Ah[f][2 + hh] = ex2h2(eB) & amaskB;
                    }
                }
                int sw0 = (jp0 + r)     ^ (q << 2);
                int sw1 = (jp0 + 4 + r) ^ (q << 2);
#pragma unroll
                for (int nt = 0; nt < 2; nt++) {
                    int base = (nt*8 + q) * 512;
                    uint32_t bh0 = Vh[base + sw0], bh1 = Vh[base + sw1];
#pragma unroll
                    for (int f = 0; f < 2; f++)
                        mma16h(acc[f][nt], Ah[f], bh0, bh1);
                }
#pragma unroll
                for (int f = 0; f < 2; f++)
                    mma16h(accz[f], Ah[f], ONES16, ONES16);
            }
        }
    }

    // cross-jseg reduction through smem (stride 21 -> conflict-free)
    if (jseg > 0) {
        float* dp = red + (((jseg - 1)*4 + rw)*32 + lane)*21;
        int c = 0;
#pragma unroll
        for (int f = 0; f < 2; f++)
#pragma unroll
            for (int nt = 0; nt < 2; nt++)
#pragma unroll
                for (int i = 0; i < 4; i++) dp[c++] = acc[f][nt][i];
        dp[16] = accz[0][0]; dp[17] = accz[0][2];
        dp[18] = accz[1][0]; dp[19] = accz[1][2];
    }
    __syncthreads();
    if (jseg == 0) {
        float z00 = accz[0][0], z02 = accz[0][2], z10 = accz[1][0], z12 = accz[1][2];
#pragma unroll
        for (int s = 0; s < 3; s++) {
            const float* sp = red + ((s*4 + rw)*32 + lane)*21;
            int c = 0;
#pragma unroll
            for (int f = 0; f < 2; f++)
#pragma unroll
                for (int nt = 0; nt < 2; nt++)
#pragma unroll
                    for (int i = 0; i < 4; i++) acc[f][nt][i] += sp[c++];
            z00 += sp[16]; z02 += sp[17]; z10 += sp[18]; z12 += sp[19];
        }
        float zz[2][2] = {{z00, z02}, {z10, z12}};
#pragma unroll
        for (int f = 0; f < 2; f++) {
#pragma unroll
            for (int hh = 0; hh < 2; hh++) {
                int row = row0 + rw*32 + q + 16*f + 8*hh;
                float inv = 1.f / zz[f][hh];
#pragma unroll
                for (int nt = 0; nt < 2; nt++) {
                    int col = nt*8 + 2*r;
                    if (nt == 0 || r < 2) {
                        float2 v;
                        v.x = eluf(acc[f][nt][2*hh]*inv);
                        v.y = eluf(acc[f][nt][2*hh + 1]*inv);
                        *(float2*)(out + (size_t)b*NN*NP + (size_t)row*NP + col) = v;
                    }
                }
            }
        }
    }
}

// ---------------- launch ----------------
extern "C" void kernel_launch(void* const* d_in, const int* in_sizes, int n_in,
                              void* d_out, int out_size) {
    const float* x         = (const float*)d_in[0];
    const int*   adj       = (const int*)  d_in[1];
    const float* W         = (const float*)d_in[2];
    const float* a_src     = (const float*)d_in[3];
    const float* a_dst     = (const float*)d_in[4];
    const float* W_out     = (const float*)d_in[5];
    const float* a_out_src = (const float*)d_in[6];
    const float* a_out_dst = (const float*)d_in[7];
    float* out = (float*)d_out;

    int smem1 = (32*512 + 512 + NHID*NP) * (int)sizeof(float);            // 69120 B
    int smem2 = (16*512 + 512 + NN + 3*4*32*21) * (int)sizeof(float);     // 71168 B
    cudaFuncSetAttribute(k_attn1_f, cudaFuncAttributeMaxDynamicSharedMemorySize, smem1);
    cudaFuncSetAttribute(k_attn2_m, cudaFuncAttributeMaxDynamicSharedMemorySize, smem2);

    k_mask<<<NN, NN>>>(adj);
    k_wh<<<dim3(B*HEADS, NN/256), 256>>>(x, W, a_src, a_dst);
    k_attn1_f<<<B*HEADS*2, 512, smem1>>>(W_out);
    k_attn2_m<<<B*8, 512, smem2>>>(out, a_out_src, a_out_dst);
}